// round 6
// baseline (speedup 1.0000x reference)
#include <cuda_runtime.h>
#include <cuda_bf16.h>
#include <cstdint>

#define NPX 1024
#define NE 1984
#define KTOP 256
#define NIMG 24
#define SINK_ITERS 150
#define CLU 4

__device__ float g_v[NIMG][NPX];
__device__ float g_bd[NIMG][2][2][KTOP];
__device__ float g_wpart[NIMG * CLU];

__device__ __forceinline__ unsigned ordf(float f) {
    unsigned u = __float_as_uint(f);
    return (u & 0x80000000u) ? ~u : (u | 0x80000000u);
}

__device__ __forceinline__ float blkMax(float v, float* r8) {
    #pragma unroll
    for (int o = 16; o; o >>= 1) v = fmaxf(v, __shfl_xor_sync(0xffffffffu, v, o));
    if ((threadIdx.x & 31) == 0) r8[threadIdx.x >> 5] = v;
    __syncthreads();
    float m = r8[0];
    #pragma unroll
    for (int k = 1; k < 8; ++k) m = fmaxf(m, r8[k]);
    __syncthreads();
    return m;
}
__device__ __forceinline__ float blkSum(float v, float* r8) {
    #pragma unroll
    for (int o = 16; o; o >>= 1) v += __shfl_xor_sync(0xffffffffu, v, o);
    if ((threadIdx.x & 31) == 0) r8[threadIdx.x >> 5] = v;
    __syncthreads();
    float s = r8[0];
    #pragma unroll
    for (int k = 1; k < 8; ++k) s += r8[k];
    __syncthreads();
    return s;
}

__device__ __forceinline__ void edge_uv(int e, int& u, int& v) {
    if (e < 992) { int rr = e / 31, cc = e - rr * 31; u = rr * 32 + cc; v = u + 1; }
    else { u = e - 992; v = u + 32; }
}

__device__ void bitonic2048(unsigned long long* keys) {
    int tid = threadIdx.x;
    for (unsigned k = 2; k <= 2048; k <<= 1)
        for (unsigned j = k >> 1; j > 0; j >>= 1) {
            __syncthreads();
            for (unsigned i = tid; i < 2048; i += 256) {
                unsigned l = i ^ j;
                if (l > i) {
                    unsigned long long a = keys[i], b = keys[l];
                    bool up = ((i & k) == 0);
                    if ((a > b) == up) { keys[i] = b; keys[l] = a; }
                }
            }
        }
    __syncthreads();
}

__device__ __forceinline__ uint32_t smem_u32(const void* p) {
    uint32_t a;
    asm("{ .reg .u64 t; cvta.to.shared.u64 t, %1; cvt.u32.u64 %0, t; }" : "=r"(a) : "l"(p));
    return a;
}
__device__ __forceinline__ uint32_t mapa_u32(uint32_t addr, int rank) {
    uint32_t r;
    asm("mapa.shared::cluster.u32 %0, %1, %2;" : "=r"(r) : "r"(addr), "r"(rank));
    return r;
}
__device__ __forceinline__ void st_async_f32(uint32_t raddr, float v, uint32_t rmbar) {
    asm volatile("st.async.shared::cluster.mbarrier::complete_tx::bytes.b32 [%0], %1, [%2];"
                 :: "r"(raddr), "f"(v), "r"(rmbar) : "memory");
}
__device__ __forceinline__ void mbar_init(uint32_t mb, uint32_t cnt) {
    asm volatile("mbarrier.init.shared.b64 [%0], %1;" :: "r"(mb), "r"(cnt) : "memory");
}
__device__ __forceinline__ void mbar_expect(uint32_t mb, uint32_t bytes) {
    asm volatile("mbarrier.arrive.expect_tx.shared.b64 _, [%0], %1;"
                 :: "r"(mb), "r"(bytes) : "memory");
}
__device__ __forceinline__ void mbar_wait(uint32_t mb, uint32_t parity) {
    uint32_t done;
    asm volatile(
        "{\n\t.reg .pred p;\n\t"
        "mbarrier.try_wait.parity.acquire.cta.shared::cta.b64 p, [%1], %2;\n\t"
        "selp.b32 %0, 1, 0, p;\n\t}"
        : "=r"(done) : "r"(mb), "r"(parity) : "memory");
    while (!done) {
        asm volatile(
            "{\n\t.reg .pred p;\n\t"
            "mbarrier.try_wait.parity.acquire.cta.shared::cta.b64 p, [%1], %2, 0x989680;\n\t"
            "selp.b32 %0, 1, 0, p;\n\t}"
            : "=r"(done) : "r"(mb), "r"(parity) : "memory");
    }
}
#define CLUSTER_SYNC() do { \
    asm volatile("barrier.cluster.arrive.aligned;" ::: "memory"); \
    asm volatile("barrier.cluster.wait.aligned;" ::: "memory"); } while (0)

// ---------------- stage 1: softmax + one-hot + pool ----------------
__global__ void pool_kernel(const float* __restrict__ x, const int* __restrict__ y) {
    int idx = blockIdx.x * blockDim.x + threadIdx.x;
    if (idx >= NIMG * NPX) return;
    int m = idx >> 10, cell = idx & 1023;
    int gi = cell >> 5, gj = cell & 31;
    float acc = 0.f;
    if (m < 12) {
        int b = m / 3, c = m % 3 + 1;
        const float* xb = x + (size_t)b * 4 * 65536;
        for (int pi = 0; pi < 8; ++pi) {
            int off0 = (gi * 8 + pi) * 256 + gj * 8;
            #pragma unroll
            for (int pj = 0; pj < 8; ++pj) {
                int off = off0 + pj;
                float x0 = xb[off], x1 = xb[65536 + off],
                      x2 = xb[131072 + off], x3 = xb[196608 + off];
                float mx = fmaxf(fmaxf(x0, x1), fmaxf(x2, x3));
                float e0 = __expf(x0 - mx), e1 = __expf(x1 - mx),
                      e2 = __expf(x2 - mx), e3 = __expf(x3 - mx);
                float ec = (c == 1) ? e1 : ((c == 2) ? e2 : e3);
                acc += ec / (e0 + e1 + e2 + e3);
            }
        }
    } else {
        int mm = m - 12, b = mm / 3, c = mm % 3 + 1;
        const int* yb = y + (size_t)b * 65536;
        int cnt = 0;
        for (int pi = 0; pi < 8; ++pi) {
            int off0 = (gi * 8 + pi) * 256 + gj * 8;
            #pragma unroll
            for (int pj = 0; pj < 8; ++pj) cnt += (yb[off0 + pj] == c);
        }
        acc = (float)cnt;
    }
    g_v[m][cell] = acc * 0.015625f;
}

// ---------------- stage 2: persistence diagrams ----------------
__global__ void diagram_kernel() {
    int m = blockIdx.x >> 1;
    int r = blockIdx.x & 1;
    __shared__ float v[NPX];
    __shared__ unsigned long long keys[2048];
    __shared__ float bArr[2048], dArr[2048];
    __shared__ int parent[NPX];
    __shared__ float birth[NPX];
    __shared__ float r8[8];
    __shared__ int sRu[32], sRv[32];
    __shared__ float sW[32];
    int tid = threadIdx.x;

    for (int i = tid; i < NPX; i += 256) {
        float val = g_v[m][i];
        if (r) val = -val;
        v[i] = val; birth[i] = val; parent[i] = i;
    }
    __syncthreads();

    for (int e = tid; e < 2048; e += 256) {
        unsigned long long key = ~0ULL;
        if (e < NE) {
            int u, w2; edge_uv(e, u, w2);
            float w = fmaxf(v[u], v[w2]);
            key = ((unsigned long long)ordf(w) << 32) | (unsigned)e;
        }
        keys[e] = key;
    }
    float mn = v[tid], mx = v[tid];
    for (int i = tid + 256; i < NPX; i += 256) { mn = fminf(mn, v[i]); mx = fmaxf(mx, v[i]); }

    bitonic2048(keys);
    float vmax = blkMax(mx, r8);
    float vmin = -blkMax(-mn, r8);

    // warp-assisted exact Kruskal: lanes pre-find roots into smem stage,
    // lane 0 re-validates and commits in exact sorted order.
    if (tid < 32) {
        for (int base = 0; base < NE; base += 32) {   // NE = 62*32
            int s = base + tid;
            int e = (int)(unsigned)keys[s];
            int u, vv; edge_uv(e, u, vv);
            float w = fmaxf(v[u], v[vv]);
            int ru = u;
            for (;;) { int p = parent[ru]; if (p == ru) break;
                       int g2 = parent[p]; parent[ru] = g2; ru = g2; }
            int rv = vv;
            for (;;) { int p = parent[rv]; if (p == rv) break;
                       int g2 = parent[p]; parent[rv] = g2; rv = g2; }
            sRu[tid] = ru; sRv[tid] = rv; sW[tid] = w;
            __syncwarp();
            if (tid == 0) {
                #pragma unroll 4
                for (int l = 0; l < 32; ++l) {
                    int ra = sRu[l], rb = sRv[l];
                    float wl = sW[l];
                    while (parent[ra] != ra) ra = parent[ra];
                    while (parent[rb] != rb) rb = parent[rb];
                    float b, d;
                    if (ra == rb) { b = wl; d = wl; }
                    else {
                        float ba = birth[ra], bb2 = birth[rb];
                        b = fmaxf(ba, bb2); d = wl;
                        if (ba <= bb2) { parent[rb] = ra; birth[ra] = fminf(ba, bb2); }
                        else           { parent[ra] = rb; birth[rb] = fminf(ba, bb2); }
                    }
                    bArr[base + l] = b; dArr[base + l] = d;
                }
            }
            __syncwarp();
        }
        if (tid == 0 && r == 0) { bArr[NE] = vmin; dArr[NE] = vmax; }
    }
    __syncthreads();

    int limit = (r == 0) ? NE + 1 : NE;
    for (int e = tid; e < 2048; e += 256) {
        unsigned long long key = ~0ULL;
        if (e < limit) {
            float pval = dArr[e] - bArr[e];
            key = ((unsigned long long)(~ordf(pval)) << 32) | (unsigned)e;
        }
        keys[e] = key;
    }
    bitonic2048(keys);

    if (tid < KTOP) {
        int s = (int)(unsigned)keys[tid];
        if (r == 0) {
            g_bd[m][0][0][tid] = bArr[s];
            g_bd[m][0][1][tid] = dArr[s];
        } else {
            g_bd[m][1][0][tid] = -dArr[s];
            g_bd[m][1][1][tid] = -bArr[s];
        }
    }
}

// ---------------- stage 3: factorized clustered Sinkhorn ----------------
// Transposed E (row stride 68 floats: conflict-free LDS.128), float4 dot,
// st.async + mbarrier tx-count exchange (no barrier.cluster in the loop).
#define ETSTRIDE 68
#define OFF_EFT 0                          // EfT [256][68]
#define OFF_EGT (256 * ETSTRIDE)           // EgT [256][68]
#define OFF_PBF (2 * 256 * ETSTRIDE)       // [256][4]
#define OFF_PBG (OFF_PBF + 1024)
#define OFF_F   (OFF_PBG + 1024)
#define OFF_G   (OFF_F + 256)
#define OFF_EXG (OFF_G + 256)
#define OFF_EXF (OFF_EXG + 256)
#define OFF_EDA (OFF_EXF + 256)
#define OFF_EDB (OFF_EDA + 256)
#define OFF_DAS (OFF_EDB + 256)
#define OFF_DBS (OFF_DAS + 256)
#define OFF_A   (OFF_DBS + 256)            // float2[256]
#define OFF_B   (OFF_A + 512)
#define OFF_RED (OFF_B + 512)
#define OFF_SC  (OFF_RED + 8)              // [0]=F2 [1]=G2 [2]=EF2 [3]=EG2
#define OFF_MB  (OFF_SC + 4)               // 2x u64 mbarrier (8B aligned: OFF_MB even)
#define SINK_SMEM_FLOATS (OFF_MB + 4)

__global__ void __cluster_dims__(CLU, 1, 1) sinkhorn_kernel() {
    extern __shared__ float sm[];
    float* EfT = sm + OFF_EFT;
    float* EgT = sm + OFF_EGT;
    float* pbf = sm + OFF_PBF;
    float* pbg = sm + OFF_PBG;
    float* F = sm + OFF_F;
    float* G = sm + OFF_G;
    float* EG = sm + OFF_EXG;
    float* EF = sm + OFF_EXF;
    float* EDA = sm + OFF_EDA;
    float* EDB = sm + OFF_EDB;
    float* das = sm + OFF_DAS;
    float* dbs = sm + OFF_DBS;
    float2* Ash = (float2*)(sm + OFF_A);
    float2* Bsh = (float2*)(sm + OFF_B);
    float* r8 = sm + OFF_RED;
    float* sc = sm + OFF_SC;

    int t = threadIdx.x;
    int p = blockIdx.x >> 2;
    int q = blockIdx.x & 3;
    int q64 = q * 64;
    int dim = (p < 12) ? 0 : 1;
    int img = (p < 12) ? p : p - 12;

    uint32_t mbf = smem_u32(sm + OFF_MB);
    uint32_t mbg = mbf + 8;
    if (t == 0) { mbar_init(mbf, 1); mbar_init(mbg, 1); }

    float ab = g_bd[img][dim][0][t],      ad = g_bd[img][dim][1][t];
    float bb = g_bd[12 + img][dim][0][t], bd = g_bd[12 + img][dim][1][t];
    float2 a = make_float2(ab, ad), b = make_float2(bb, bd);
    Ash[t] = a; Bsh[t] = b;
    float da = 0.5f * (ad - ab), db = 0.5f * (bd - bb);
    F[t] = 0.f; G[t] = 0.f; EG[t] = 1.f;
    if (t < 4) sc[t] = (t < 2) ? 0.f : 1.f;
    __syncthreads();

    float mC = fmaxf(da, db);
    #pragma unroll 4
    for (int i = 0; i < KTOP; ++i) {
        float2 aq = Ash[i];
        mC = fmaxf(mC, fmaxf(fabsf(aq.x - b.x), fabsf(aq.y - b.y)));
    }
    float eps = 0.02f * fmaxf(blkMax(mC, r8), 1e-6f);
    float ie = 1.f / eps;
    das[t] = da * ie; dbs[t] = db * ie;
    EDA[t] = __expf(-da * ie); EDB[t] = __expf(-db * ie);

    // transposed scaled kernels: EfT[t][jj] = exp(-C(t, q64+jj)/eps)
    #pragma unroll 4
    for (int k = 0; k < 16; ++k) {
        float4 e;
        {
            float2 b0 = Bsh[q64 + k * 4 + 0], b1 = Bsh[q64 + k * 4 + 1],
                   b2 = Bsh[q64 + k * 4 + 2], b3 = Bsh[q64 + k * 4 + 3];
            e.x = __expf(-fmaxf(fabsf(a.x - b0.x), fabsf(a.y - b0.y)) * ie);
            e.y = __expf(-fmaxf(fabsf(a.x - b1.x), fabsf(a.y - b1.y)) * ie);
            e.z = __expf(-fmaxf(fabsf(a.x - b2.x), fabsf(a.y - b2.y)) * ie);
            e.w = __expf(-fmaxf(fabsf(a.x - b3.x), fabsf(a.y - b3.y)) * ie);
        }
        *(float4*)&EfT[t * ETSTRIDE + k * 4] = e;
        float4 g4;
        {
            float2 a0 = Ash[q64 + k * 4 + 0], a1 = Ash[q64 + k * 4 + 1],
                   a2 = Ash[q64 + k * 4 + 2], a3 = Ash[q64 + k * 4 + 3];
            g4.x = __expf(-fmaxf(fabsf(a0.x - b.x), fabsf(a0.y - b.y)) * ie);
            g4.y = __expf(-fmaxf(fabsf(a1.x - b.x), fabsf(a1.y - b.y)) * ie);
            g4.z = __expf(-fmaxf(fabsf(a2.x - b.x), fabsf(a2.y - b.y)) * ie);
            g4.w = __expf(-fmaxf(fabsf(a3.x - b.x), fabsf(a3.y - b.y)) * ie);
        }
        *(float4*)&EgT[t * ETSTRIDE + k * 4] = g4;
    }
    __syncthreads();
    CLUSTER_SYNC();          // mbarrier init + tiles visible cluster-wide

    uint32_t rpbf[CLU], rpbg[CLU], rmbf[CLU], rmbg[CLU];
    {
        uint32_t lf = smem_u32(&pbf[t * 4 + q]);
        uint32_t lg = smem_u32(&pbg[t * 4 + q]);
        #pragma unroll
        for (int rr = 0; rr < CLU; ++rr) {
            rpbf[rr] = mapa_u32(lf, rr); rmbf[rr] = mapa_u32(mbf, rr);
            rpbg[rr] = mapa_u32(lg, rr); rmbg[rr] = mapa_u32(mbg, rr);
        }
    }
    float K_G = 0.f, K_F;
    float myEDA = EDA[t], myEDB = EDB[t];
    const float4* EGv = (const float4*)(EG + q64);
    const float4* EFv = (const float4*)(EF + q64);

    for (int it = 0; it < SINK_ITERS; ++it) {
        uint32_t par = (uint32_t)(it & 1);
        // ---- f half-iter: s = sum_j EG_j * EfT[t][j] ----
        float4 acc = make_float4(0.f, 0.f, 0.f, 0.f);
        #pragma unroll
        for (int k = 0; k < 16; ++k) {
            float4 e = *(const float4*)&EfT[t * ETSTRIDE + k * 4];
            float4 g4 = EGv[k];
            acc.x = fmaf(g4.x, e.x, acc.x);
            acc.y = fmaf(g4.y, e.y, acc.y);
            acc.z = fmaf(g4.z, e.z, acc.z);
            acc.w = fmaf(g4.w, e.w, acc.w);
        }
        float s = (acc.x + acc.y) + (acc.z + acc.w);
        #pragma unroll
        for (int rr = 0; rr < CLU; ++rr) st_async_f32(rpbf[rr], s, rmbf[rr]);
        if (t < 32) {                       // warp0: F2 (full 256, local — EG replicated)
            float s2 = 0.f;
            #pragma unroll
            for (int k = 0; k < 8; ++k) { int j = t + k * 32; s2 = fmaf(EG[j], EDB[j], s2); }
            #pragma unroll
            for (int o = 16; o; o >>= 1) s2 += __shfl_xor_sync(0xffffffffu, s2, o);
            if (t == 0) {
                sc[0] = -(K_G + __logf(s2 + 256.f * sc[3]));
                mbar_expect(mbf, 4096);
            }
        }
        mbar_wait(mbf, par);
        {
            float4 pb4 = *(const float4*)&pbf[t * 4];
            float S = ((pb4.x + pb4.y) + (pb4.z + pb4.w)) + 256.f * sc[3] * myEDA;
            float phiF = -(K_G + __logf(S));
            F[t] = phiF;
            K_F = blkMax(phiF, r8);
            EF[t] = __expf(phiF - K_F);
            if (t == 0) sc[2] = __expf(sc[0] - K_F);
        }
        __syncthreads();

        // ---- g half-iter ----
        acc = make_float4(0.f, 0.f, 0.f, 0.f);
        #pragma unroll
        for (int k = 0; k < 16; ++k) {
            float4 e = *(const float4*)&EgT[t * ETSTRIDE + k * 4];
            float4 f4 = EFv[k];
            acc.x = fmaf(f4.x, e.x, acc.x);
            acc.y = fmaf(f4.y, e.y, acc.y);
            acc.z = fmaf(f4.z, e.z, acc.z);
            acc.w = fmaf(f4.w, e.w, acc.w);
        }
        s = (acc.x + acc.y) + (acc.z + acc.w);
        #pragma unroll
        for (int rr = 0; rr < CLU; ++rr) st_async_f32(rpbg[rr], s, rmbg[rr]);
        if (t < 32) {                       // warp0: G2
            float s2 = 0.f;
            #pragma unroll
            for (int k = 0; k < 8; ++k) { int i = t + k * 32; s2 = fmaf(EF[i], EDA[i], s2); }
            #pragma unroll
            for (int o = 16; o; o >>= 1) s2 += __shfl_xor_sync(0xffffffffu, s2, o);
            if (t == 0) {
                sc[1] = -(K_F + __logf(s2 + 256.f * sc[2]));
                mbar_expect(mbg, 4096);
            }
        }
        mbar_wait(mbg, par);
        {
            float4 pb4 = *(const float4*)&pbg[t * 4];
            float S = ((pb4.x + pb4.y) + (pb4.z + pb4.w)) + 256.f * sc[2] * myEDB;
            float phiG = -(K_F + __logf(S));
            G[t] = phiG;
            K_G = blkMax(phiG, r8);
            EG[t] = __expf(phiG - K_G);
            if (t == 0) sc[3] = __expf(sc[1] - K_G);
        }
        __syncthreads();
    }

    // ---- final cost partial: i-chunk rows + chunked rank-1 terms ----
    float acc2 = 0.f;
    float myG = G[t];
    #pragma unroll 4
    for (int ii = 0; ii < 64; ++ii) {
        float2 aq = Ash[q64 + ii];
        float cs = fmaxf(fabsf(aq.x - b.x), fabsf(aq.y - b.y)) * ie;
        acc2 += __expf(F[q64 + ii] + myG - cs) * cs;
    }
    if (t < 64) {
        int i = q64 + t;
        acc2 += 256.f * __expf(F[i] + sc[1] - das[i]) * das[i];
        acc2 += 256.f * __expf(sc[0] + G[i] - dbs[i]) * dbs[i];
    }
    float tot = blkSum(acc2, r8);
    if (t == 0) g_wpart[p * CLU + q] = tot * eps;
    CLUSTER_SYNC();          // exit safety
}

// ---------------- stage 4: deterministic reduction ----------------
__global__ void final_kernel(float* out) {
    float s = 0.f;
    for (int p = 0; p < NIMG; ++p) {
        float w = 0.f;
        for (int q = 0; q < CLU; ++q) w += g_wpart[p * CLU + q];
        s += w;
    }
    out[0] = s * 0.25f;
}

extern "C" void kernel_launch(void* const* d_in, const int* in_sizes, int n_in,
                              void* d_out, int out_size) {
    (void)in_sizes; (void)n_in; (void)out_size;
    const float* x = (const float*)d_in[0];
    const int* y = (const int*)d_in[1];
    static bool attr_set = false;
    if (!attr_set) {
        cudaFuncSetAttribute(sinkhorn_kernel,
                             cudaFuncAttributeMaxDynamicSharedMemorySize,
                             SINK_SMEM_FLOATS * 4);
        attr_set = true;
    }
    pool_kernel<<<(NIMG * NPX + 255) / 256, 256>>>(x, y);
    diagram_kernel<<<48, 256>>>();
    sinkhorn_kernel<<<NIMG * CLU, 256, SINK_SMEM_FLOATS * 4>>>();
    final_kernel<<<1, 1>>>((float*)d_out);
}

// round 7
// speedup vs baseline: 1.0121x; 1.0121x over previous
#include <cuda_runtime.h>
#include <cuda_bf16.h>
#include <cstdint>

#define NPX 1024
#define NE 1984
#define KTOP 256
#define NIMG 24
#define SINK_ITERS 150
#define CLU 4

__device__ float g_v[NIMG][NPX];
__device__ float g_bd[NIMG][2][2][KTOP];
__device__ float g_wpart[NIMG * CLU];

__device__ __forceinline__ unsigned ordf(float f) {
    unsigned u = __float_as_uint(f);
    return (u & 0x80000000u) ? ~u : (u | 0x80000000u);
}

__device__ __forceinline__ float blkMax(float v, float* r8) {
    #pragma unroll
    for (int o = 16; o; o >>= 1) v = fmaxf(v, __shfl_xor_sync(0xffffffffu, v, o));
    if ((threadIdx.x & 31) == 0) r8[threadIdx.x >> 5] = v;
    __syncthreads();
    float m = r8[0];
    #pragma unroll
    for (int k = 1; k < 8; ++k) m = fmaxf(m, r8[k]);
    __syncthreads();
    return m;
}
__device__ __forceinline__ float blkSum(float v, float* r8) {
    #pragma unroll
    for (int o = 16; o; o >>= 1) v += __shfl_xor_sync(0xffffffffu, v, o);
    if ((threadIdx.x & 31) == 0) r8[threadIdx.x >> 5] = v;
    __syncthreads();
    float s = r8[0];
    #pragma unroll
    for (int k = 1; k < 8; ++k) s += r8[k];
    __syncthreads();
    return s;
}

__device__ __forceinline__ void edge_uv(int e, int& u, int& v) {
    if (e < 992) { int rr = e / 31, cc = e - rr * 31; u = rr * 32 + cc; v = u + 1; }
    else { u = e - 992; v = u + 32; }
}

__device__ void bitonic2048(unsigned long long* keys) {
    int tid = threadIdx.x;
    for (unsigned k = 2; k <= 2048; k <<= 1)
        for (unsigned j = k >> 1; j > 0; j >>= 1) {
            __syncthreads();
            for (unsigned i = tid; i < 2048; i += 256) {
                unsigned l = i ^ j;
                if (l > i) {
                    unsigned long long a = keys[i], b = keys[l];
                    bool up = ((i & k) == 0);
                    if ((a > b) == up) { keys[i] = b; keys[l] = a; }
                }
            }
        }
    __syncthreads();
}

__device__ __forceinline__ uint32_t smem_u32(const void* p) {
    uint32_t a;
    asm("{ .reg .u64 t; cvta.to.shared.u64 t, %1; cvt.u32.u64 %0, t; }" : "=r"(a) : "l"(p));
    return a;
}
__device__ __forceinline__ uint32_t mapa_u32(uint32_t addr, int rank) {
    uint32_t r;
    asm("mapa.shared::cluster.u32 %0, %1, %2;" : "=r"(r) : "r"(addr), "r"(rank));
    return r;
}
__device__ __forceinline__ void st_cluster_f32(uint32_t raddr, float v) {
    asm volatile("st.shared::cluster.b32 [%0], %1;" :: "r"(raddr), "f"(v) : "memory");
}
__device__ __forceinline__ void mbar_init(uint32_t mb, uint32_t cnt) {
    asm volatile("mbarrier.init.shared.b64 [%0], %1;" :: "r"(mb), "r"(cnt) : "memory");
}
__device__ __forceinline__ void mbar_arrive_remote(uint32_t rmb) {
    asm volatile("mbarrier.arrive.shared::cluster.b64 _, [%0];" :: "r"(rmb) : "memory");
}
__device__ __forceinline__ void mbar_wait(uint32_t mb, uint32_t parity) {
    uint32_t done;
    asm volatile(
        "{\n\t.reg .pred p;\n\t"
        "mbarrier.try_wait.parity.shared.b64 p, [%1], %2;\n\t"
        "selp.b32 %0, 1, 0, p;\n\t}"
        : "=r"(done) : "r"(mb), "r"(parity) : "memory");
    while (!done) {
        asm volatile(
            "{\n\t.reg .pred p;\n\t"
            "mbarrier.try_wait.parity.shared.b64 p, [%1], %2, 0x989680;\n\t"
            "selp.b32 %0, 1, 0, p;\n\t}"
            : "=r"(done) : "r"(mb), "r"(parity) : "memory");
    }
}
#define FENCE_CLUSTER() asm volatile("fence.acq_rel.cluster;" ::: "memory")
#define CLUSTER_SYNC() do { \
    asm volatile("barrier.cluster.arrive.aligned;" ::: "memory"); \
    asm volatile("barrier.cluster.wait.aligned;" ::: "memory"); } while (0)

// ---------------- stage 1: softmax + one-hot + pool ----------------
__global__ void pool_kernel(const float* __restrict__ x, const int* __restrict__ y) {
    int idx = blockIdx.x * blockDim.x + threadIdx.x;
    if (idx >= NIMG * NPX) return;
    int m = idx >> 10, cell = idx & 1023;
    int gi = cell >> 5, gj = cell & 31;
    float acc = 0.f;
    if (m < 12) {
        int b = m / 3, c = m % 3 + 1;
        const float* xb = x + (size_t)b * 4 * 65536;
        for (int pi = 0; pi < 8; ++pi) {
            int off0 = (gi * 8 + pi) * 256 + gj * 8;
            #pragma unroll
            for (int pj = 0; pj < 8; ++pj) {
                int off = off0 + pj;
                float x0 = xb[off], x1 = xb[65536 + off],
                      x2 = xb[131072 + off], x3 = xb[196608 + off];
                float mx = fmaxf(fmaxf(x0, x1), fmaxf(x2, x3));
                float e0 = __expf(x0 - mx), e1 = __expf(x1 - mx),
                      e2 = __expf(x2 - mx), e3 = __expf(x3 - mx);
                float ec = (c == 1) ? e1 : ((c == 2) ? e2 : e3);
                acc += ec / (e0 + e1 + e2 + e3);
            }
        }
    } else {
        int mm = m - 12, b = mm / 3, c = mm % 3 + 1;
        const int* yb = y + (size_t)b * 65536;
        int cnt = 0;
        for (int pi = 0; pi < 8; ++pi) {
            int off0 = (gi * 8 + pi) * 256 + gj * 8;
            #pragma unroll
            for (int pj = 0; pj < 8; ++pj) cnt += (yb[off0 + pj] == c);
        }
        acc = (float)cnt;
    }
    g_v[m][cell] = acc * 0.015625f;
}

// ---------------- stage 2: persistence diagrams ----------------
__global__ void diagram_kernel() {
    int m = blockIdx.x >> 1;
    int r = blockIdx.x & 1;
    __shared__ float v[NPX];
    __shared__ unsigned long long keys[2048];
    __shared__ float bArr[2048], dArr[2048];
    __shared__ int parent[NPX];
    __shared__ float birth[NPX];
    __shared__ float r8[8];
    __shared__ int sRu[32], sRv[32];
    __shared__ float sW[32];
    int tid = threadIdx.x;

    for (int i = tid; i < NPX; i += 256) {
        float val = g_v[m][i];
        if (r) val = -val;
        v[i] = val; birth[i] = val; parent[i] = i;
    }
    __syncthreads();

    for (int e = tid; e < 2048; e += 256) {
        unsigned long long key = ~0ULL;
        if (e < NE) {
            int u, w2; edge_uv(e, u, w2);
            float w = fmaxf(v[u], v[w2]);
            key = ((unsigned long long)ordf(w) << 32) | (unsigned)e;
        }
        keys[e] = key;
    }
    float mn = v[tid], mx = v[tid];
    for (int i = tid + 256; i < NPX; i += 256) { mn = fminf(mn, v[i]); mx = fmaxf(mx, v[i]); }

    bitonic2048(keys);
    float vmax = blkMax(mx, r8);
    float vmin = -blkMax(-mn, r8);

    // warp-assisted exact Kruskal: lanes pre-find roots into smem stage,
    // lane 0 re-validates and commits in exact sorted order.
    if (tid < 32) {
        for (int base = 0; base < NE; base += 32) {   // NE = 62*32
            int s = base + tid;
            int e = (int)(unsigned)keys[s];
            int u, vv; edge_uv(e, u, vv);
            float w = fmaxf(v[u], v[vv]);
            int ru = u;
            for (;;) { int p = parent[ru]; if (p == ru) break;
                       int g2 = parent[p]; parent[ru] = g2; ru = g2; }
            int rv = vv;
            for (;;) { int p = parent[rv]; if (p == rv) break;
                       int g2 = parent[p]; parent[rv] = g2; rv = g2; }
            sRu[tid] = ru; sRv[tid] = rv; sW[tid] = w;
            __syncwarp();
            if (tid == 0) {
                #pragma unroll 4
                for (int l = 0; l < 32; ++l) {
                    int ra = sRu[l], rb = sRv[l];
                    float wl = sW[l];
                    while (parent[ra] != ra) ra = parent[ra];
                    while (parent[rb] != rb) rb = parent[rb];
                    float b, d;
                    if (ra == rb) { b = wl; d = wl; }
                    else {
                        float ba = birth[ra], bb2 = birth[rb];
                        b = fmaxf(ba, bb2); d = wl;
                        if (ba <= bb2) { parent[rb] = ra; birth[ra] = fminf(ba, bb2); }
                        else           { parent[ra] = rb; birth[rb] = fminf(ba, bb2); }
                    }
                    bArr[base + l] = b; dArr[base + l] = d;
                }
            }
            __syncwarp();
        }
        if (tid == 0 && r == 0) { bArr[NE] = vmin; dArr[NE] = vmax; }
    }
    __syncthreads();

    int limit = (r == 0) ? NE + 1 : NE;
    for (int e = tid; e < 2048; e += 256) {
        unsigned long long key = ~0ULL;
        if (e < limit) {
            float pval = dArr[e] - bArr[e];
            key = ((unsigned long long)(~ordf(pval)) << 32) | (unsigned)e;
        }
        keys[e] = key;
    }
    bitonic2048(keys);

    if (tid < KTOP) {
        int s = (int)(unsigned)keys[tid];
        if (r == 0) {
            g_bd[m][0][0][tid] = bArr[s];
            g_bd[m][0][1][tid] = dArr[s];
        } else {
            g_bd[m][1][0][tid] = -dArr[s];
            g_bd[m][1][1][tid] = -bArr[s];
        }
    }
}

// ---------------- stage 3: factorized clustered Sinkhorn ----------------
// Transposed E (stride-68 rows, conflict-free LDS.128), float4 dot.
// Exchange: plain st.shared::cluster; sync: count-4 mbarrier (1 remote arrive
// per CTA per rank) + cluster fences. No barrier.cluster in the loop.
#define ETSTRIDE 68
#define OFF_EFT 0                          // EfT [256][68]
#define OFF_EGT (256 * ETSTRIDE)           // EgT [256][68]
#define OFF_PBF (2 * 256 * ETSTRIDE)       // [256][4]
#define OFF_PBG (OFF_PBF + 1024)
#define OFF_F   (OFF_PBG + 1024)
#define OFF_G   (OFF_F + 256)
#define OFF_EXG (OFF_G + 256)
#define OFF_EXF (OFF_EXG + 256)
#define OFF_EDA (OFF_EXF + 256)
#define OFF_EDB (OFF_EDA + 256)
#define OFF_DAS (OFF_EDB + 256)
#define OFF_DBS (OFF_DAS + 256)
#define OFF_A   (OFF_DBS + 256)            // float2[256]
#define OFF_B   (OFF_A + 512)
#define OFF_RED (OFF_B + 512)
#define OFF_SC  (OFF_RED + 8)              // [0]=F2 [1]=G2 [2]=EF2 [3]=EG2
#define OFF_MB  (OFF_SC + 4)               // 2x u64 mbarrier
#define SINK_SMEM_FLOATS (OFF_MB + 4)

__global__ void __cluster_dims__(CLU, 1, 1) sinkhorn_kernel() {
    extern __shared__ float sm[];
    float* EfT = sm + OFF_EFT;
    float* EgT = sm + OFF_EGT;
    float* pbf = sm + OFF_PBF;
    float* pbg = sm + OFF_PBG;
    float* F = sm + OFF_F;
    float* G = sm + OFF_G;
    float* EG = sm + OFF_EXG;
    float* EF = sm + OFF_EXF;
    float* EDA = sm + OFF_EDA;
    float* EDB = sm + OFF_EDB;
    float* das = sm + OFF_DAS;
    float* dbs = sm + OFF_DBS;
    float2* Ash = (float2*)(sm + OFF_A);
    float2* Bsh = (float2*)(sm + OFF_B);
    float* r8 = sm + OFF_RED;
    float* sc = sm + OFF_SC;

    int t = threadIdx.x;
    int p = blockIdx.x >> 2;
    int q = blockIdx.x & 3;
    int q64 = q * 64;
    int dim = (p < 12) ? 0 : 1;
    int img = (p < 12) ? p : p - 12;

    uint32_t mbf = smem_u32(sm + OFF_MB);
    uint32_t mbg = mbf + 8;
    if (t == 0) { mbar_init(mbf, CLU); mbar_init(mbg, CLU); }

    float ab = g_bd[img][dim][0][t],      ad = g_bd[img][dim][1][t];
    float bb = g_bd[12 + img][dim][0][t], bd = g_bd[12 + img][dim][1][t];
    float2 a = make_float2(ab, ad), b = make_float2(bb, bd);
    Ash[t] = a; Bsh[t] = b;
    float da = 0.5f * (ad - ab), db = 0.5f * (bd - bb);
    F[t] = 0.f; G[t] = 0.f; EG[t] = 1.f;
    if (t < 4) sc[t] = (t < 2) ? 0.f : 1.f;
    __syncthreads();

    float mC = fmaxf(da, db);
    #pragma unroll 4
    for (int i = 0; i < KTOP; ++i) {
        float2 aq = Ash[i];
        mC = fmaxf(mC, fmaxf(fabsf(aq.x - b.x), fabsf(aq.y - b.y)));
    }
    float eps = 0.02f * fmaxf(blkMax(mC, r8), 1e-6f);
    float ie = 1.f / eps;
    das[t] = da * ie; dbs[t] = db * ie;
    EDA[t] = __expf(-da * ie); EDB[t] = __expf(-db * ie);

    // transposed scaled kernels: EfT[t][jj] = exp(-C(t, q64+jj)/eps)
    #pragma unroll 4
    for (int k = 0; k < 16; ++k) {
        float4 e;
        {
            float2 b0 = Bsh[q64 + k * 4 + 0], b1 = Bsh[q64 + k * 4 + 1],
                   b2 = Bsh[q64 + k * 4 + 2], b3 = Bsh[q64 + k * 4 + 3];
            e.x = __expf(-fmaxf(fabsf(a.x - b0.x), fabsf(a.y - b0.y)) * ie);
            e.y = __expf(-fmaxf(fabsf(a.x - b1.x), fabsf(a.y - b1.y)) * ie);
            e.z = __expf(-fmaxf(fabsf(a.x - b2.x), fabsf(a.y - b2.y)) * ie);
            e.w = __expf(-fmaxf(fabsf(a.x - b3.x), fabsf(a.y - b3.y)) * ie);
        }
        *(float4*)&EfT[t * ETSTRIDE + k * 4] = e;
        float4 g4;
        {
            float2 a0 = Ash[q64 + k * 4 + 0], a1 = Ash[q64 + k * 4 + 1],
                   a2 = Ash[q64 + k * 4 + 2], a3 = Ash[q64 + k * 4 + 3];
            g4.x = __expf(-fmaxf(fabsf(a0.x - b.x), fabsf(a0.y - b.y)) * ie);
            g4.y = __expf(-fmaxf(fabsf(a1.x - b.x), fabsf(a1.y - b.y)) * ie);
            g4.z = __expf(-fmaxf(fabsf(a2.x - b.x), fabsf(a2.y - b.y)) * ie);
            g4.w = __expf(-fmaxf(fabsf(a3.x - b.x), fabsf(a3.y - b.y)) * ie);
        }
        *(float4*)&EgT[t * ETSTRIDE + k * 4] = g4;
    }
    __syncthreads();
    CLUSTER_SYNC();          // mbarrier init + tiles visible cluster-wide

    uint32_t rpbf[CLU], rpbg[CLU], rmbf[CLU], rmbg[CLU];
    {
        uint32_t lf = smem_u32(&pbf[t * 4 + q]);
        uint32_t lg = smem_u32(&pbg[t * 4 + q]);
        #pragma unroll
        for (int rr = 0; rr < CLU; ++rr) {
            rpbf[rr] = mapa_u32(lf, rr); rmbf[rr] = mapa_u32(mbf, rr);
            rpbg[rr] = mapa_u32(lg, rr); rmbg[rr] = mapa_u32(mbg, rr);
        }
    }
    float K_G = 0.f, K_F;
    float myEDA = EDA[t], myEDB = EDB[t];
    const float4* EGv = (const float4*)(EG + q64);
    const float4* EFv = (const float4*)(EF + q64);

    for (int it = 0; it < SINK_ITERS; ++it) {
        uint32_t par = (uint32_t)(it & 1);
        // ---- f half-iter: s = sum_j EG_j * EfT[t][j] ----
        float4 acc = make_float4(0.f, 0.f, 0.f, 0.f);
        #pragma unroll
        for (int k = 0; k < 16; ++k) {
            float4 e = *(const float4*)&EfT[t * ETSTRIDE + k * 4];
            float4 g4 = EGv[k];
            acc.x = fmaf(g4.x, e.x, acc.x);
            acc.y = fmaf(g4.y, e.y, acc.y);
            acc.z = fmaf(g4.z, e.z, acc.z);
            acc.w = fmaf(g4.w, e.w, acc.w);
        }
        float s = (acc.x + acc.y) + (acc.z + acc.w);
        #pragma unroll
        for (int rr = 0; rr < CLU; ++rr) st_cluster_f32(rpbf[rr], s);
        if (t < 32) {                       // warp0: F2 (full 256, local — EG replicated)
            float s2 = 0.f;
            #pragma unroll
            for (int k = 0; k < 8; ++k) { int j = t + k * 32; s2 = fmaf(EG[j], EDB[j], s2); }
            #pragma unroll
            for (int o = 16; o; o >>= 1) s2 += __shfl_xor_sync(0xffffffffu, s2, o);
            if (t == 0) sc[0] = -(K_G + __logf(s2 + 256.f * sc[3]));
        }
        __syncthreads();                    // all remote stores + sc[0] ordered
        if (t == 0) {
            FENCE_CLUSTER();
            #pragma unroll
            for (int rr = 0; rr < CLU; ++rr) mbar_arrive_remote(rmbf[rr]);
        }
        mbar_wait(mbf, par);
        FENCE_CLUSTER();
        {
            float4 pb4 = *(const float4*)&pbf[t * 4];
            float S = ((pb4.x + pb4.y) + (pb4.z + pb4.w)) + 256.f * sc[3] * myEDA;
            float phiF = -(K_G + __logf(S));
            F[t] = phiF;
            K_F = blkMax(phiF, r8);
            EF[t] = __expf(phiF - K_F);
            if (t == 0) sc[2] = __expf(sc[0] - K_F);
        }
        __syncthreads();

        // ---- g half-iter ----
        acc = make_float4(0.f, 0.f, 0.f, 0.f);
        #pragma unroll
        for (int k = 0; k < 16; ++k) {
            float4 e = *(const float4*)&EgT[t * ETSTRIDE + k * 4];
            float4 f4 = EFv[k];
            acc.x = fmaf(f4.x, e.x, acc.x);
            acc.y = fmaf(f4.y, e.y, acc.y);
            acc.z = fmaf(f4.z, e.z, acc.z);
            acc.w = fmaf(f4.w, e.w, acc.w);
        }
        s = (acc.x + acc.y) + (acc.z + acc.w);
        #pragma unroll
        for (int rr = 0; rr < CLU; ++rr) st_cluster_f32(rpbg[rr], s);
        if (t < 32) {                       // warp0: G2
            float s2 = 0.f;
            #pragma unroll
            for (int k = 0; k < 8; ++k) { int i = t + k * 32; s2 = fmaf(EF[i], EDA[i], s2); }
            #pragma unroll
            for (int o = 16; o; o >>= 1) s2 += __shfl_xor_sync(0xffffffffu, s2, o);
            if (t == 0) sc[1] = -(K_F + __logf(s2 + 256.f * sc[2]));
        }
        __syncthreads();
        if (t == 0) {
            FENCE_CLUSTER();
            #pragma unroll
            for (int rr = 0; rr < CLU; ++rr) mbar_arrive_remote(rmbg[rr]);
        }
        mbar_wait(mbg, par);
        FENCE_CLUSTER();
        {
            float4 pb4 = *(const float4*)&pbg[t * 4];
            float S = ((pb4.x + pb4.y) + (pb4.z + pb4.w)) + 256.f * sc[2] * myEDB;
            float phiG = -(K_F + __logf(S));
            G[t] = phiG;
            K_G = blkMax(phiG, r8);
            EG[t] = __expf(phiG - K_G);
            if (t == 0) sc[3] = __expf(sc[1] - K_G);
        }
        __syncthreads();
    }

    // ---- final cost partial: i-chunk rows + chunked rank-1 terms ----
    float acc2 = 0.f;
    float myG = G[t];
    #pragma unroll 4
    for (int ii = 0; ii < 64; ++ii) {
        float2 aq = Ash[q64 + ii];
        float cs = fmaxf(fabsf(aq.x - b.x), fabsf(aq.y - b.y)) * ie;
        acc2 += __expf(F[q64 + ii] + myG - cs) * cs;
    }
    if (t < 64) {
        int i = q64 + t;
        acc2 += 256.f * __expf(F[i] + sc[1] - das[i]) * das[i];
        acc2 += 256.f * __expf(sc[0] + G[i] - dbs[i]) * dbs[i];
    }
    float tot = blkSum(acc2, r8);
    if (t == 0) g_wpart[p * CLU + q] = tot * eps;
    CLUSTER_SYNC();          // exit safety: no CTA leaves with peer stores in flight
}

// ---------------- stage 4: deterministic reduction ----------------
__global__ void final_kernel(float* out) {
    float s = 0.f;
    for (int p = 0; p < NIMG; ++p) {
        float w = 0.f;
        for (int q = 0; q < CLU; ++q) w += g_wpart[p * CLU + q];
        s += w;
    }
    out[0] = s * 0.25f;
}

extern "C" void kernel_launch(void* const* d_in, const int* in_sizes, int n_in,
                              void* d_out, int out_size) {
    (void)in_sizes; (void)n_in; (void)out_size;
    const float* x = (const float*)d_in[0];
    const int* y = (const int*)d_in[1];
    static bool attr_set = false;
    if (!attr_set) {
        cudaFuncSetAttribute(sinkhorn_kernel,
                             cudaFuncAttributeMaxDynamicSharedMemorySize,
                             SINK_SMEM_FLOATS * 4);
        attr_set = true;
    }
    pool_kernel<<<(NIMG * NPX + 255) / 256, 256>>>(x, y);
    diagram_kernel<<<48, 256>>>();
    sinkhorn_kernel<<<NIMG * CLU, 256, SINK_SMEM_FLOATS * 4>>>();
    final_kernel<<<1, 1>>>((float*)d_out);
}

// round 8
// speedup vs baseline: 1.3654x; 1.3491x over previous
#include <cuda_runtime.h>
#include <cuda_bf16.h>
#include <cstdint>

#define NPX 1024
#define NE 1984
#define KTOP 256
#define NIMG 24
#define SINK_ITERS 150
#define CLU 4

__device__ float g_v[NIMG][NPX];
__device__ float g_bd[NIMG][2][2][KTOP];
__device__ float g_wpart[NIMG * CLU];

__device__ __forceinline__ unsigned ordf(float f) {
    unsigned u = __float_as_uint(f);
    return (u & 0x80000000u) ? ~u : (u | 0x80000000u);
}

__device__ __forceinline__ float blkMax(float v, float* r8) {
    #pragma unroll
    for (int o = 16; o; o >>= 1) v = fmaxf(v, __shfl_xor_sync(0xffffffffu, v, o));
    if ((threadIdx.x & 31) == 0) r8[threadIdx.x >> 5] = v;
    __syncthreads();
    float m = r8[0];
    #pragma unroll
    for (int k = 1; k < 8; ++k) m = fmaxf(m, r8[k]);
    __syncthreads();
    return m;
}
__device__ __forceinline__ float blkSum(float v, float* r8) {
    #pragma unroll
    for (int o = 16; o; o >>= 1) v += __shfl_xor_sync(0xffffffffu, v, o);
    if ((threadIdx.x & 31) == 0) r8[threadIdx.x >> 5] = v;
    __syncthreads();
    float s = r8[0];
    #pragma unroll
    for (int k = 1; k < 8; ++k) s += r8[k];
    __syncthreads();
    return s;
}

__device__ __forceinline__ void edge_uv(int e, int& u, int& v) {
    if (e < 992) { int rr = e / 31, cc = e - rr * 31; u = rr * 32 + cc; v = u + 1; }
    else { u = e - 992; v = u + 32; }
}

__device__ void bitonic2048(unsigned long long* keys) {
    int tid = threadIdx.x;
    for (unsigned k = 2; k <= 2048; k <<= 1)
        for (unsigned j = k >> 1; j > 0; j >>= 1) {
            __syncthreads();
            for (unsigned i = tid; i < 2048; i += 256) {
                unsigned l = i ^ j;
                if (l > i) {
                    unsigned long long a = keys[i], b = keys[l];
                    bool up = ((i & k) == 0);
                    if ((a > b) == up) { keys[i] = b; keys[l] = a; }
                }
            }
        }
    __syncthreads();
}

__device__ __forceinline__ uint32_t smem_u32(const void* p) {
    uint32_t a;
    asm("{ .reg .u64 t; cvta.to.shared.u64 t, %1; cvt.u32.u64 %0, t; }" : "=r"(a) : "l"(p));
    return a;
}
__device__ __forceinline__ void st_cluster_f32(uint32_t addr, int rank, float v) {
    uint32_t r;
    asm volatile("mapa.shared::cluster.u32 %0, %1, %2;" : "=r"(r) : "r"(addr), "r"(rank));
    asm volatile("st.shared::cluster.b32 [%0], %1;" :: "r"(r), "f"(v) : "memory");
}
#define CLUSTER_SYNC() do { \
    asm volatile("barrier.cluster.arrive.aligned;" ::: "memory"); \
    asm volatile("barrier.cluster.wait.aligned;" ::: "memory"); } while (0)

// ---------------- stage 1: softmax + one-hot + pool ----------------
__global__ void pool_kernel(const float* __restrict__ x, const int* __restrict__ y) {
    int idx = blockIdx.x * blockDim.x + threadIdx.x;
    if (idx >= NIMG * NPX) return;
    int m = idx >> 10, cell = idx & 1023;
    int gi = cell >> 5, gj = cell & 31;
    float acc = 0.f;
    if (m < 12) {
        int b = m / 3, c = m % 3 + 1;
        const float* xb = x + (size_t)b * 4 * 65536;
        for (int pi = 0; pi < 8; ++pi) {
            int off0 = (gi * 8 + pi) * 256 + gj * 8;
            #pragma unroll
            for (int pj = 0; pj < 8; ++pj) {
                int off = off0 + pj;
                float x0 = xb[off], x1 = xb[65536 + off],
                      x2 = xb[131072 + off], x3 = xb[196608 + off];
                float mx = fmaxf(fmaxf(x0, x1), fmaxf(x2, x3));
                float e0 = __expf(x0 - mx), e1 = __expf(x1 - mx),
                      e2 = __expf(x2 - mx), e3 = __expf(x3 - mx);
                float ec = (c == 1) ? e1 : ((c == 2) ? e2 : e3);
                acc += ec / (e0 + e1 + e2 + e3);
            }
        }
    } else {
        int mm = m - 12, b = mm / 3, c = mm % 3 + 1;
        const int* yb = y + (size_t)b * 65536;
        int cnt = 0;
        for (int pi = 0; pi < 8; ++pi) {
            int off0 = (gi * 8 + pi) * 256 + gj * 8;
            #pragma unroll
            for (int pj = 0; pj < 8; ++pj) cnt += (yb[off0 + pj] == c);
        }
        acc = (float)cnt;
    }
    g_v[m][cell] = acc * 0.015625f;
}

// ---------------- stage 2: persistence diagrams ----------------
__global__ void diagram_kernel() {
    int m = blockIdx.x >> 1;
    int r = blockIdx.x & 1;
    __shared__ float v[NPX];
    __shared__ unsigned long long keys[2048];
    __shared__ float bArr[2048], dArr[2048];
    __shared__ int parent[NPX];
    __shared__ float birth[NPX];
    __shared__ float r8[8];
    __shared__ int sRu[32], sRv[32];
    __shared__ float sW[32];
    int tid = threadIdx.x;

    for (int i = tid; i < NPX; i += 256) {
        float val = g_v[m][i];
        if (r) val = -val;
        v[i] = val; birth[i] = val; parent[i] = i;
    }
    __syncthreads();

    for (int e = tid; e < 2048; e += 256) {
        unsigned long long key = ~0ULL;
        if (e < NE) {
            int u, w2; edge_uv(e, u, w2);
            float w = fmaxf(v[u], v[w2]);
            key = ((unsigned long long)ordf(w) << 32) | (unsigned)e;
        }
        keys[e] = key;
    }
    float mn = v[tid], mx = v[tid];
    for (int i = tid + 256; i < NPX; i += 256) { mn = fminf(mn, v[i]); mx = fmaxf(mx, v[i]); }

    bitonic2048(keys);
    float vmax = blkMax(mx, r8);
    float vmin = -blkMax(-mn, r8);

    if (tid < 32) {
        for (int base = 0; base < NE; base += 32) {
            int s = base + tid;
            int e = (int)(unsigned)keys[s];
            int u, vv; edge_uv(e, u, vv);
            float w = fmaxf(v[u], v[vv]);
            int ru = u;
            for (;;) { int p = parent[ru]; if (p == ru) break;
                       int g2 = parent[p]; parent[ru] = g2; ru = g2; }
            int rv = vv;
            for (;;) { int p = parent[rv]; if (p == rv) break;
                       int g2 = parent[p]; parent[rv] = g2; rv = g2; }
            sRu[tid] = ru; sRv[tid] = rv; sW[tid] = w;
            __syncwarp();
            if (tid == 0) {
                #pragma unroll 4
                for (int l = 0; l < 32; ++l) {
                    int ra = sRu[l], rb = sRv[l];
                    float wl = sW[l];
                    while (parent[ra] != ra) ra = parent[ra];
                    while (parent[rb] != rb) rb = parent[rb];
                    float b, d;
                    if (ra == rb) { b = wl; d = wl; }
                    else {
                        float ba = birth[ra], bb2 = birth[rb];
                        b = fmaxf(ba, bb2); d = wl;
                        if (ba <= bb2) { parent[rb] = ra; birth[ra] = fminf(ba, bb2); }
                        else           { parent[ra] = rb; birth[rb] = fminf(ba, bb2); }
                    }
                    bArr[base + l] = b; dArr[base + l] = d;
                }
            }
            __syncwarp();
        }
        if (tid == 0 && r == 0) { bArr[NE] = vmin; dArr[NE] = vmax; }
    }
    __syncthreads();

    int limit = (r == 0) ? NE + 1 : NE;
    for (int e = tid; e < 2048; e += 256) {
        unsigned long long key = ~0ULL;
        if (e < limit) {
            float pval = dArr[e] - bArr[e];
            key = ((unsigned long long)(~ordf(pval)) << 32) | (unsigned)e;
        }
        keys[e] = key;
    }
    bitonic2048(keys);

    if (tid < KTOP) {
        int s = (int)(unsigned)keys[tid];
        if (r == 0) {
            g_bd[m][0][0][tid] = bArr[s];
            g_bd[m][0][1][tid] = dArr[s];
        } else {
            g_bd[m][1][0][tid] = -dArr[s];
            g_bd[m][1][1][tid] = -bArr[s];
        }
    }
}

// ---------------- stage 3: factorized clustered Sinkhorn ----------------
// R5 sync/exchange (coalesced st.shared::cluster + barrier.cluster) with
// transposed-E float4 dot (stride-68 rows, conflict-free LDS.128).
#define ETSTRIDE 68
#define OFF_EFT 0                          // EfT [256][68]
#define OFF_EGT (256 * ETSTRIDE)           // EgT [256][68]
#define OFF_PBF (2 * 256 * ETSTRIDE)       // [4][256] coalesced
#define OFF_PBG (OFF_PBF + 1024)
#define OFF_F   (OFF_PBG + 1024)
#define OFF_G   (OFF_F + 256)
#define OFF_EXG (OFF_G + 256)
#define OFF_EXF (OFF_EXG + 256)
#define OFF_EDA (OFF_EXF + 256)
#define OFF_EDB (OFF_EDA + 256)
#define OFF_DAS (OFF_EDB + 256)
#define OFF_DBS (OFF_DAS + 256)
#define OFF_A   (OFF_DBS + 256)            // float2[256]
#define OFF_B   (OFF_A + 512)
#define OFF_RED (OFF_B + 512)
#define OFF_SC  (OFF_RED + 8)              // [0]=F2 [1]=G2 [2]=EF2 [3]=EG2
#define SINK_SMEM_FLOATS (OFF_SC + 4)

__global__ void __cluster_dims__(CLU, 1, 1) sinkhorn_kernel() {
    extern __shared__ float sm[];
    float* EfT = sm + OFF_EFT;
    float* EgT = sm + OFF_EGT;
    float* pbf = sm + OFF_PBF;
    float* pbg = sm + OFF_PBG;
    float* F = sm + OFF_F;
    float* G = sm + OFF_G;
    float* EG = sm + OFF_EXG;
    float* EF = sm + OFF_EXF;
    float* EDA = sm + OFF_EDA;
    float* EDB = sm + OFF_EDB;
    float* das = sm + OFF_DAS;
    float* dbs = sm + OFF_DBS;
    float2* Ash = (float2*)(sm + OFF_A);
    float2* Bsh = (float2*)(sm + OFF_B);
    float* r8 = sm + OFF_RED;
    float* sc = sm + OFF_SC;

    int t = threadIdx.x;
    int p = blockIdx.x >> 2;
    int q = blockIdx.x & 3;
    int q64 = q * 64;
    int dim = (p < 12) ? 0 : 1;
    int img = (p < 12) ? p : p - 12;

    float ab = g_bd[img][dim][0][t],      ad = g_bd[img][dim][1][t];
    float bb = g_bd[12 + img][dim][0][t], bd = g_bd[12 + img][dim][1][t];
    float2 a = make_float2(ab, ad), b = make_float2(bb, bd);
    Ash[t] = a; Bsh[t] = b;
    float da = 0.5f * (ad - ab), db = 0.5f * (bd - bb);
    F[t] = 0.f; G[t] = 0.f; EG[t] = 1.f;
    if (t < 4) sc[t] = (t < 2) ? 0.f : 1.f;
    __syncthreads();

    float mC = fmaxf(da, db);
    #pragma unroll 4
    for (int i = 0; i < KTOP; ++i) {
        float2 aq = Ash[i];
        mC = fmaxf(mC, fmaxf(fabsf(aq.x - b.x), fabsf(aq.y - b.y)));
    }
    float eps = 0.02f * fmaxf(blkMax(mC, r8), 1e-6f);
    float ie = 1.f / eps;
    das[t] = da * ie; dbs[t] = db * ie;
    EDA[t] = __expf(-da * ie); EDB[t] = __expf(-db * ie);

    // transposed scaled kernels: EfT[t][jj] = exp(-C(t, q64+jj)/eps)
    #pragma unroll 4
    for (int k = 0; k < 16; ++k) {
        float4 e;
        {
            float2 b0 = Bsh[q64 + k * 4 + 0], b1 = Bsh[q64 + k * 4 + 1],
                   b2 = Bsh[q64 + k * 4 + 2], b3 = Bsh[q64 + k * 4 + 3];
            e.x = __expf(-fmaxf(fabsf(a.x - b0.x), fabsf(a.y - b0.y)) * ie);
            e.y = __expf(-fmaxf(fabsf(a.x - b1.x), fabsf(a.y - b1.y)) * ie);
            e.z = __expf(-fmaxf(fabsf(a.x - b2.x), fabsf(a.y - b2.y)) * ie);
            e.w = __expf(-fmaxf(fabsf(a.x - b3.x), fabsf(a.y - b3.y)) * ie);
        }
        *(float4*)&EfT[t * ETSTRIDE + k * 4] = e;
        float4 g4;
        {
            float2 a0 = Ash[q64 + k * 4 + 0], a1 = Ash[q64 + k * 4 + 1],
                   a2 = Ash[q64 + k * 4 + 2], a3 = Ash[q64 + k * 4 + 3];
            g4.x = __expf(-fmaxf(fabsf(a0.x - b.x), fabsf(a0.y - b.y)) * ie);
            g4.y = __expf(-fmaxf(fabsf(a1.x - b.x), fabsf(a1.y - b.y)) * ie);
            g4.z = __expf(-fmaxf(fabsf(a2.x - b.x), fabsf(a2.y - b.y)) * ie);
            g4.w = __expf(-fmaxf(fabsf(a3.x - b.x), fabsf(a3.y - b.y)) * ie);
        }
        *(float4*)&EgT[t * ETSTRIDE + k * 4] = g4;
    }
    __syncthreads();
    CLUSTER_SYNC();

    uint32_t pbf_addr = smem_u32(&pbf[q * 256 + t]);   // coalesced remote stores
    uint32_t pbg_addr = smem_u32(&pbg[q * 256 + t]);
    float K_G = 0.f, K_F;
    float myEDA = EDA[t], myEDB = EDB[t];
    const float4* EGv = (const float4*)(EG + q64);
    const float4* EFv = (const float4*)(EF + q64);

    for (int it = 0; it < SINK_ITERS; ++it) {
        // ---- f half-iter: s = sum_j EG_j * EfT[t][j] ----
        float4 acc = make_float4(0.f, 0.f, 0.f, 0.f);
        #pragma unroll
        for (int k = 0; k < 16; ++k) {
            float4 e = *(const float4*)&EfT[t * ETSTRIDE + k * 4];
            float4 g4 = EGv[k];
            acc.x = fmaf(g4.x, e.x, acc.x);
            acc.y = fmaf(g4.y, e.y, acc.y);
            acc.z = fmaf(g4.z, e.z, acc.z);
            acc.w = fmaf(g4.w, e.w, acc.w);
        }
        float s = (acc.x + acc.y) + (acc.z + acc.w);
        #pragma unroll
        for (int rr = 0; rr < CLU; ++rr) st_cluster_f32(pbf_addr, rr, s);
        if (t < 32) {                       // warp0: F2 (full 256, local — EG replicated)
            float s2 = 0.f;
            #pragma unroll
            for (int k = 0; k < 8; ++k) { int j = t + k * 32; s2 = fmaf(EG[j], EDB[j], s2); }
            #pragma unroll
            for (int o = 16; o; o >>= 1) s2 += __shfl_xor_sync(0xffffffffu, s2, o);
            if (t == 0) sc[0] = -(K_G + __logf(s2 + 256.f * sc[3]));
        }
        CLUSTER_SYNC();
        {
            float S = ((pbf[t] + pbf[256 + t]) + (pbf[512 + t] + pbf[768 + t]))
                    + 256.f * sc[3] * myEDA;
            float phiF = -(K_G + __logf(S));
            F[t] = phiF;
            K_F = blkMax(phiF, r8);
            EF[t] = __expf(phiF - K_F);
            if (t == 0) sc[2] = __expf(sc[0] - K_F);
        }
        __syncthreads();

        // ---- g half-iter ----
        acc = make_float4(0.f, 0.f, 0.f, 0.f);
        #pragma unroll
        for (int k = 0; k < 16; ++k) {
            float4 e = *(const float4*)&EgT[t * ETSTRIDE + k * 4];
            float4 f4 = EFv[k];
            acc.x = fmaf(f4.x, e.x, acc.x);
            acc.y = fmaf(f4.y, e.y, acc.y);
            acc.z = fmaf(f4.z, e.z, acc.z);
            acc.w = fmaf(f4.w, e.w, acc.w);
        }
        s = (acc.x + acc.y) + (acc.z + acc.w);
        #pragma unroll
        for (int rr = 0; rr < CLU; ++rr) st_cluster_f32(pbg_addr, rr, s);
        if (t < 32) {                       // warp0: G2
            float s2 = 0.f;
            #pragma unroll
            for (int k = 0; k < 8; ++k) { int i = t + k * 32; s2 = fmaf(EF[i], EDA[i], s2); }
            #pragma unroll
            for (int o = 16; o; o >>= 1) s2 += __shfl_xor_sync(0xffffffffu, s2, o);
            if (t == 0) sc[1] = -(K_F + __logf(s2 + 256.f * sc[2]));
        }
        CLUSTER_SYNC();
        {
            float S = ((pbg[t] + pbg[256 + t]) + (pbg[512 + t] + pbg[768 + t]))
                    + 256.f * sc[2] * myEDB;
            float phiG = -(K_F + __logf(S));
            G[t] = phiG;
            K_G = blkMax(phiG, r8);
            EG[t] = __expf(phiG - K_G);
            if (t == 0) sc[3] = __expf(sc[1] - K_G);
        }
        __syncthreads();
    }

    // ---- final cost partial ----
    float acc2 = 0.f;
    float myG = G[t];
    #pragma unroll 4
    for (int ii = 0; ii < 64; ++ii) {
        float2 aq = Ash[q64 + ii];
        float cs = fmaxf(fabsf(aq.x - b.x), fabsf(aq.y - b.y)) * ie;
        acc2 += __expf(F[q64 + ii] + myG - cs) * cs;
    }
    if (t < 64) {
        int i = q64 + t;
        acc2 += 256.f * __expf(F[i] + sc[1] - das[i]) * das[i];
        acc2 += 256.f * __expf(sc[0] + G[i] - dbs[i]) * dbs[i];
    }
    float tot = blkSum(acc2, r8);
    if (t == 0) g_wpart[p * CLU + q] = tot * eps;
}

// ---------------- stage 4: deterministic reduction ----------------
__global__ void final_kernel(float* out) {
    float s = 0.f;
    for (int p = 0; p < NIMG; ++p) {
        float w = 0.f;
        for (int q = 0; q < CLU; ++q) w += g_wpart[p * CLU + q];
        s += w;
    }
    out[0] = s * 0.25f;
}

extern "C" void kernel_launch(void* const* d_in, const int* in_sizes, int n_in,
                              void* d_out, int out_size) {
    (void)in_sizes; (void)n_in; (void)out_size;
    const float* x = (const float*)d_in[0];
    const int* y = (const int*)d_in[1];
    static bool attr_set = false;
    if (!attr_set) {
        cudaFuncSetAttribute(sinkhorn_kernel,
                             cudaFuncAttributeMaxDynamicSharedMemorySize,
                             SINK_SMEM_FLOATS * 4);
        attr_set = true;
    }
    pool_kernel<<<(NIMG * NPX + 255) / 256, 256>>>(x, y);
    diagram_kernel<<<48, 256>>>();
    sinkhorn_kernel<<<NIMG * CLU, 256, SINK_SMEM_FLOATS * 4>>>();
    final_kernel<<<1, 1>>>((float*)d_out);
}

// round 9
// speedup vs baseline: 1.5157x; 1.1101x over previous
#include <cuda_runtime.h>
#include <cuda_bf16.h>
#include <cstdint>

#define NPX 1024
#define NE 1984
#define KTOP 256
#define NIMG 24
#define SINK_ITERS 150
#define CLU 4

__device__ float g_v[NIMG][NPX];
__device__ float g_bd[NIMG][2][2][KTOP];
__device__ float g_wpart[NIMG * CLU];
__device__ int g_ctr;

__device__ __forceinline__ unsigned ordf(float f) {
    unsigned u = __float_as_uint(f);
    return (u & 0x80000000u) ? ~u : (u | 0x80000000u);
}

__device__ __forceinline__ float blkMax(float v, float* r8) {
    #pragma unroll
    for (int o = 16; o; o >>= 1) v = fmaxf(v, __shfl_xor_sync(0xffffffffu, v, o));
    if ((threadIdx.x & 31) == 0) r8[threadIdx.x >> 5] = v;
    __syncthreads();
    float m = r8[0];
    #pragma unroll
    for (int k = 1; k < 8; ++k) m = fmaxf(m, r8[k]);
    __syncthreads();
    return m;
}
__device__ __forceinline__ float blkSum(float v, float* r8) {
    #pragma unroll
    for (int o = 16; o; o >>= 1) v += __shfl_xor_sync(0xffffffffu, v, o);
    if ((threadIdx.x & 31) == 0) r8[threadIdx.x >> 5] = v;
    __syncthreads();
    float s = r8[0];
    #pragma unroll
    for (int k = 1; k < 8; ++k) s += r8[k];
    __syncthreads();
    return s;
}

__device__ __forceinline__ void edge_uv(int e, int& u, int& v) {
    if (e < 992) { int rr = e / 31, cc = e - rr * 31; u = rr * 32 + cc; v = u + 1; }
    else { u = e - 992; v = u + 32; }
}

__device__ void bitonic2048(unsigned long long* keys) {
    int tid = threadIdx.x;
    for (unsigned k = 2; k <= 2048; k <<= 1)
        for (unsigned j = k >> 1; j > 0; j >>= 1) {
            __syncthreads();
            for (unsigned i = tid; i < 2048; i += 256) {
                unsigned l = i ^ j;
                if (l > i) {
                    unsigned long long a = keys[i], b = keys[l];
                    bool up = ((i & k) == 0);
                    if ((a > b) == up) { keys[i] = b; keys[l] = a; }
                }
            }
        }
    __syncthreads();
}

__device__ __forceinline__ uint32_t smem_u32(const void* p) {
    uint32_t a;
    asm("{ .reg .u64 t; cvta.to.shared.u64 t, %1; cvt.u32.u64 %0, t; }" : "=r"(a) : "l"(p));
    return a;
}
__device__ __forceinline__ void st_cluster_f32(uint32_t addr, int rank, float v) {
    uint32_t r;
    asm volatile("mapa.shared::cluster.u32 %0, %1, %2;" : "=r"(r) : "r"(addr), "r"(rank));
    asm volatile("st.shared::cluster.b32 [%0], %1;" :: "r"(r), "f"(v) : "memory");
}
#define CLUSTER_SYNC() do { \
    asm volatile("barrier.cluster.arrive.aligned;" ::: "memory"); \
    asm volatile("barrier.cluster.wait.aligned;" ::: "memory"); } while (0)

// ---------------- stage 1: softmax + one-hot + pool ----------------
__global__ void pool_kernel(const float* __restrict__ x, const int* __restrict__ y) {
    int idx = blockIdx.x * blockDim.x + threadIdx.x;
    if (idx >= NIMG * NPX) return;
    int m = idx >> 10, cell = idx & 1023;
    int gi = cell >> 5, gj = cell & 31;
    float acc = 0.f;
    if (m < 12) {
        int b = m / 3, c = m % 3 + 1;
        const float* xb = x + (size_t)b * 4 * 65536;
        for (int pi = 0; pi < 8; ++pi) {
            int off0 = (gi * 8 + pi) * 256 + gj * 8;
            #pragma unroll
            for (int pj = 0; pj < 8; ++pj) {
                int off = off0 + pj;
                float x0 = xb[off], x1 = xb[65536 + off],
                      x2 = xb[131072 + off], x3 = xb[196608 + off];
                float mx = fmaxf(fmaxf(x0, x1), fmaxf(x2, x3));
                float e0 = __expf(x0 - mx), e1 = __expf(x1 - mx),
                      e2 = __expf(x2 - mx), e3 = __expf(x3 - mx);
                float ec = (c == 1) ? e1 : ((c == 2) ? e2 : e3);
                acc += ec / (e0 + e1 + e2 + e3);
            }
        }
    } else {
        int mm = m - 12, b = mm / 3, c = mm % 3 + 1;
        const int* yb = y + (size_t)b * 65536;
        int cnt = 0;
        for (int pi = 0; pi < 8; ++pi) {
            int off0 = (gi * 8 + pi) * 256 + gj * 8;
            #pragma unroll
            for (int pj = 0; pj < 8; ++pj) cnt += (yb[off0 + pj] == c);
        }
        acc = (float)cnt;
    }
    g_v[m][cell] = acc * 0.015625f;
}

// ---------------- stage 2: persistence diagrams ----------------
// birth[x] == v[x] invariant: reference's birth update is always a self-no-op
// (older root keeps the min birth by definition), so no birth array at all.
__global__ void diagram_kernel() {
    int m = blockIdx.x >> 1;
    int r = blockIdx.x & 1;
    __shared__ float v[NPX];
    __shared__ unsigned long long keys[2048];
    __shared__ float bArr[2048], dArr[2048];
    __shared__ int parent[NPX];
    __shared__ float r8[8];
    __shared__ int sRu[32], sRv[32];
    __shared__ float sW[32], sBu[32], sBv[32];
    int tid = threadIdx.x;

    for (int i = tid; i < NPX; i += 256) {
        float val = g_v[m][i];
        if (r) val = -val;
        v[i] = val; parent[i] = i;
    }
    __syncthreads();

    for (int e = tid; e < 2048; e += 256) {
        unsigned long long key = ~0ULL;
        if (e < NE) {
            int u, w2; edge_uv(e, u, w2);
            float w = fmaxf(v[u], v[w2]);
            key = ((unsigned long long)ordf(w) << 32) | (unsigned)e;
        }
        keys[e] = key;
    }
    float mn = v[tid], mx = v[tid];
    for (int i = tid + 256; i < NPX; i += 256) { mn = fminf(mn, v[i]); mx = fmaxf(mx, v[i]); }

    bitonic2048(keys);
    float vmax = blkMax(mx, r8);
    float vmin = -blkMax(-mn, r8);

    // warp-assisted exact Kruskal: lanes pre-find roots + stage births,
    // lane 0 re-validates (walk only if root changed) and commits in order.
    if (tid < 32) {
        for (int base = 0; base < NE; base += 32) {     // NE = 62*32
            int s = base + tid;
            int e = (int)(unsigned)keys[s];
            int u, vv; edge_uv(e, u, vv);
            float w = fmaxf(v[u], v[vv]);
            int ru = u;
            for (;;) { int p = parent[ru]; if (p == ru) break;
                       int g2 = parent[p]; parent[ru] = g2; ru = g2; }
            int rv = vv;
            for (;;) { int p = parent[rv]; if (p == rv) break;
                       int g2 = parent[p]; parent[rv] = g2; rv = g2; }
            sRu[tid] = ru; sRv[tid] = rv; sW[tid] = w;
            sBu[tid] = v[ru]; sBv[tid] = v[rv];
            __syncwarp();
            if (tid == 0) {
                #pragma unroll 4
                for (int l = 0; l < 32; ++l) {
                    int ra0 = sRu[l], rb0 = sRv[l];
                    int ra = ra0, rb = rb0;
                    float ba = sBu[l], bb2 = sBv[l];
                    int pa = parent[ra];
                    if (pa != ra) {
                        do { ra = pa; pa = parent[ra]; } while (pa != ra);
                        ba = v[ra];
                    }
                    int pb2 = parent[rb];
                    if (pb2 != rb) {
                        do { rb = pb2; pb2 = parent[rb]; } while (pb2 != rb);
                        bb2 = v[rb];
                    }
                    float wl = sW[l];
                    float b, d;
                    if (ra == rb) { b = wl; d = wl; }
                    else {
                        b = fmaxf(ba, bb2); d = wl;
                        if (ba <= bb2) parent[rb] = ra;
                        else           parent[ra] = rb;
                    }
                    bArr[base + l] = b; dArr[base + l] = d;
                }
            }
            __syncwarp();
        }
        if (tid == 0 && r == 0) { bArr[NE] = vmin; dArr[NE] = vmax; }
    }
    __syncthreads();

    int limit = (r == 0) ? NE + 1 : NE;
    for (int e = tid; e < 2048; e += 256) {
        unsigned long long key = ~0ULL;
        if (e < limit) {
            float pval = dArr[e] - bArr[e];
            key = ((unsigned long long)(~ordf(pval)) << 32) | (unsigned)e;
        }
        keys[e] = key;
    }
    bitonic2048(keys);

    if (tid < KTOP) {
        int s = (int)(unsigned)keys[tid];
        if (r == 0) {
            g_bd[m][0][0][tid] = bArr[s];
            g_bd[m][0][1][tid] = dArr[s];
        } else {
            g_bd[m][1][0][tid] = -dArr[s];
            g_bd[m][1][1][tid] = -bArr[s];
        }
    }
}

// ---------------- stage 3: factorized clustered Sinkhorn ----------------
// E slices live in REGISTERS (32 float4/thread); dot = 64 FFMA + broadcast
// LDS of EG/EF. Coalesced st.shared::cluster exchange + barrier.cluster.
// Last CTA of 96 folds the final reduction (atomic ticket, fixed-order sum).
#define OFF_PBF 0                 // [4][256]
#define OFF_PBG 1024
#define OFF_F   2048
#define OFF_G   2304
#define OFF_EXG 2560
#define OFF_EXF 2816
#define OFF_EDA 3072
#define OFF_EDB 3328
#define OFF_DAS 3584
#define OFF_DBS 3840
#define OFF_A   4096              // float2[256]
#define OFF_B   4608
#define OFF_RED 5120
#define OFF_SC  5128              // [0]=F2 [1]=G2 [2]=EF2 [3]=EG2
#define SINK_SMEM_FLOATS 5132

__global__ void __cluster_dims__(CLU, 1, 1) __launch_bounds__(256, 1)
sinkhorn_kernel(float* __restrict__ out) {
    extern __shared__ float sm[];
    float* pbf = sm + OFF_PBF;
    float* pbg = sm + OFF_PBG;
    float* F = sm + OFF_F;
    float* G = sm + OFF_G;
    float* EG = sm + OFF_EXG;
    float* EF = sm + OFF_EXF;
    float* EDA = sm + OFF_EDA;
    float* EDB = sm + OFF_EDB;
    float* das = sm + OFF_DAS;
    float* dbs = sm + OFF_DBS;
    float2* Ash = (float2*)(sm + OFF_A);
    float2* Bsh = (float2*)(sm + OFF_B);
    float* r8 = sm + OFF_RED;
    float* sc = sm + OFF_SC;

    int t = threadIdx.x;
    int p = blockIdx.x >> 2;
    int q = blockIdx.x & 3;
    int q64 = q * 64;
    int dim = (p < 12) ? 0 : 1;
    int img = (p < 12) ? p : p - 12;

    float ab = g_bd[img][dim][0][t],      ad = g_bd[img][dim][1][t];
    float bb = g_bd[12 + img][dim][0][t], bd = g_bd[12 + img][dim][1][t];
    float2 a = make_float2(ab, ad), b = make_float2(bb, bd);
    Ash[t] = a; Bsh[t] = b;
    float da = 0.5f * (ad - ab), db = 0.5f * (bd - bb);
    F[t] = 0.f; G[t] = 0.f; EG[t] = 1.f;
    if (t < 4) sc[t] = (t < 2) ? 0.f : 1.f;
    __syncthreads();

    float mC = fmaxf(da, db);
    #pragma unroll 4
    for (int i = 0; i < KTOP; ++i) {
        float2 aq = Ash[i];
        mC = fmaxf(mC, fmaxf(fabsf(aq.x - b.x), fabsf(aq.y - b.y)));
    }
    float eps = 0.02f * fmaxf(blkMax(mC, r8), 1e-6f);
    float ie = 1.f / eps;
    das[t] = da * ie; dbs[t] = db * ie;
    EDA[t] = __expf(-da * ie); EDB[t] = __expf(-db * ie);

    // register-resident scaled kernels:
    // rEf[k] = exp(-C(t, q64+4k..)/eps), rEg[k] = exp(-C(q64+4k.., t)/eps)
    float4 rEf[16], rEg[16];
    #pragma unroll
    for (int k = 0; k < 16; ++k) {
        float2 b0 = Bsh[q64 + k * 4 + 0], b1 = Bsh[q64 + k * 4 + 1],
               b2 = Bsh[q64 + k * 4 + 2], b3 = Bsh[q64 + k * 4 + 3];
        rEf[k].x = __expf(-fmaxf(fabsf(a.x - b0.x), fabsf(a.y - b0.y)) * ie);
        rEf[k].y = __expf(-fmaxf(fabsf(a.x - b1.x), fabsf(a.y - b1.y)) * ie);
        rEf[k].z = __expf(-fmaxf(fabsf(a.x - b2.x), fabsf(a.y - b2.y)) * ie);
        rEf[k].w = __expf(-fmaxf(fabsf(a.x - b3.x), fabsf(a.y - b3.y)) * ie);
        float2 a0 = Ash[q64 + k * 4 + 0], a1 = Ash[q64 + k * 4 + 1],
               a2 = Ash[q64 + k * 4 + 2], a3 = Ash[q64 + k * 4 + 3];
        rEg[k].x = __expf(-fmaxf(fabsf(a0.x - b.x), fabsf(a0.y - b.y)) * ie);
        rEg[k].y = __expf(-fmaxf(fabsf(a1.x - b.x), fabsf(a1.y - b.y)) * ie);
        rEg[k].z = __expf(-fmaxf(fabsf(a2.x - b.x), fabsf(a2.y - b.y)) * ie);
        rEg[k].w = __expf(-fmaxf(fabsf(a3.x - b.x), fabsf(a3.y - b.y)) * ie);
    }
    __syncthreads();
    CLUSTER_SYNC();

    uint32_t pbf_addr = smem_u32(&pbf[q * 256 + t]);
    uint32_t pbg_addr = smem_u32(&pbg[q * 256 + t]);
    float K_G = 0.f, K_F;
    float myEDA = EDA[t], myEDB = EDB[t];
    const float4* EGv = (const float4*)(EG + q64);
    const float4* EFv = (const float4*)(EF + q64);

    for (int it = 0; it < SINK_ITERS; ++it) {
        // ---- f half-iter: s = sum_j EG_j * Ef[t][j] ----
        float4 acc = make_float4(0.f, 0.f, 0.f, 0.f);
        #pragma unroll
        for (int k = 0; k < 16; ++k) {
            float4 g4 = EGv[k];
            acc.x = fmaf(g4.x, rEf[k].x, acc.x);
            acc.y = fmaf(g4.y, rEf[k].y, acc.y);
            acc.z = fmaf(g4.z, rEf[k].z, acc.z);
            acc.w = fmaf(g4.w, rEf[k].w, acc.w);
        }
        float s = (acc.x + acc.y) + (acc.z + acc.w);
        #pragma unroll
        for (int rr = 0; rr < CLU; ++rr) st_cluster_f32(pbf_addr, rr, s);
        if (t < 32) {                       // warp0: F2 (full, local — EG replicated)
            float s2 = 0.f;
            #pragma unroll
            for (int k = 0; k < 8; ++k) { int j = t + k * 32; s2 = fmaf(EG[j], EDB[j], s2); }
            #pragma unroll
            for (int o = 16; o; o >>= 1) s2 += __shfl_xor_sync(0xffffffffu, s2, o);
            if (t == 0) sc[0] = -(K_G + __logf(s2 + 256.f * sc[3]));
        }
        CLUSTER_SYNC();
        {
            float S = ((pbf[t] + pbf[256 + t]) + (pbf[512 + t] + pbf[768 + t]))
                    + 256.f * sc[3] * myEDA;
            float phiF = -(K_G + __logf(S));
            F[t] = phiF;
            K_F = blkMax(phiF, r8);
            EF[t] = __expf(phiF - K_F);
            if (t == 0) sc[2] = __expf(sc[0] - K_F);
        }
        __syncthreads();

        // ---- g half-iter ----
        acc = make_float4(0.f, 0.f, 0.f, 0.f);
        #pragma unroll
        for (int k = 0; k < 16; ++k) {
            float4 f4 = EFv[k];
            acc.x = fmaf(f4.x, rEg[k].x, acc.x);
            acc.y = fmaf(f4.y, rEg[k].y, acc.y);
            acc.z = fmaf(f4.z, rEg[k].z, acc.z);
            acc.w = fmaf(f4.w, rEg[k].w, acc.w);
        }
        s = (acc.x + acc.y) + (acc.z + acc.w);
        #pragma unroll
        for (int rr = 0; rr < CLU; ++rr) st_cluster_f32(pbg_addr, rr, s);
        if (t < 32) {                       // warp0: G2
            float s2 = 0.f;
            #pragma unroll
            for (int k = 0; k < 8; ++k) { int i = t + k * 32; s2 = fmaf(EF[i], EDA[i], s2); }
            #pragma unroll
            for (int o = 16; o; o >>= 1) s2 += __shfl_xor_sync(0xffffffffu, s2, o);
            if (t == 0) sc[1] = -(K_F + __logf(s2 + 256.f * sc[2]));
        }
        CLUSTER_SYNC();
        {
            float S = ((pbg[t] + pbg[256 + t]) + (pbg[512 + t] + pbg[768 + t]))
                    + 256.f * sc[2] * myEDB;
            float phiG = -(K_F + __logf(S));
            G[t] = phiG;
            K_G = blkMax(phiG, r8);
            EG[t] = __expf(phiG - K_G);
            if (t == 0) sc[3] = __expf(sc[1] - K_G);
        }
        __syncthreads();
    }

    // ---- final cost partial: i-chunk rows + chunked rank-1 terms ----
    float acc2 = 0.f;
    float myG = G[t];
    #pragma unroll 4
    for (int ii = 0; ii < 64; ++ii) {
        float2 aq = Ash[q64 + ii];
        float cs = fmaxf(fabsf(aq.x - b.x), fabsf(aq.y - b.y)) * ie;
        acc2 += __expf(F[q64 + ii] + myG - cs) * cs;
    }
    if (t < 64) {
        int i = q64 + t;
        acc2 += 256.f * __expf(F[i] + sc[1] - das[i]) * das[i];
        acc2 += 256.f * __expf(sc[0] + G[i] - dbs[i]) * dbs[i];
    }
    float tot = blkSum(acc2, r8);

    // last-CTA deterministic reduction (replaces final_kernel)
    if (t == 0) {
        g_wpart[p * CLU + q] = tot * eps;
        __threadfence();
        int ticket = atomicAdd(&g_ctr, 1);
        if (ticket == NIMG * CLU - 1) {
            g_ctr = 0;
            float ssum = 0.f;
            for (int pp = 0; pp < NIMG; ++pp) {
                float w = 0.f;
                for (int qq = 0; qq < CLU; ++qq) w += g_wpart[pp * CLU + qq];
                ssum += w;
            }
            out[0] = ssum * 0.25f;
        }
    }
}

extern "C" void kernel_launch(void* const* d_in, const int* in_sizes, int n_in,
                              void* d_out, int out_size) {
    (void)in_sizes; (void)n_in; (void)out_size;
    const float* x = (const float*)d_in[0];
    const int* y = (const int*)d_in[1];
    static bool attr_set = false;
    if (!attr_set) {
        cudaFuncSetAttribute(sinkhorn_kernel,
                             cudaFuncAttributeMaxDynamicSharedMemorySize,
                             SINK_SMEM_FLOATS * 4);
        attr_set = true;
    }
    pool_kernel<<<(NIMG * NPX + 255) / 256, 256>>>(x, y);
    diagram_kernel<<<48, 256>>>();
    sinkhorn_kernel<<<NIMG * CLU, 256, SINK_SMEM_FLOATS * 4>>>((float*)d_out);
}

// round 10
// speedup vs baseline: 1.6019x; 1.0569x over previous
#include <cuda_runtime.h>
#include <cuda_bf16.h>
#include <cstdint>

#define NPX 1024
#define NE 1984
#define KTOP 256
#define NIMG 24
#define SINK_ITERS 150
#define CLU 4
#define EXIT_TOL 1e-5f
#define MIN_ITERS 20

__device__ float g_v[NIMG][NPX];
__device__ float g_bd[NIMG][2][2][KTOP];
__device__ float g_wpart[NIMG * CLU];
__device__ int g_ctr;

__device__ __forceinline__ unsigned ordf(float f) {
    unsigned u = __float_as_uint(f);
    return (u & 0x80000000u) ? ~u : (u | 0x80000000u);
}

__device__ __forceinline__ float blkMax(float v, float* r8) {
    #pragma unroll
    for (int o = 16; o; o >>= 1) v = fmaxf(v, __shfl_xor_sync(0xffffffffu, v, o));
    if ((threadIdx.x & 31) == 0) r8[threadIdx.x >> 5] = v;
    __syncthreads();
    float m = r8[0];
    #pragma unroll
    for (int k = 1; k < 8; ++k) m = fmaxf(m, r8[k]);
    __syncthreads();
    return m;
}
__device__ __forceinline__ float blkSum(float v, float* r8) {
    #pragma unroll
    for (int o = 16; o; o >>= 1) v += __shfl_xor_sync(0xffffffffu, v, o);
    if ((threadIdx.x & 31) == 0) r8[threadIdx.x >> 5] = v;
    __syncthreads();
    float s = r8[0];
    #pragma unroll
    for (int k = 1; k < 8; ++k) s += r8[k];
    __syncthreads();
    return s;
}

__device__ __forceinline__ void edge_uv(int e, int& u, int& v) {
    if (e < 992) { int rr = e / 31, cc = e - rr * 31; u = rr * 32 + cc; v = u + 1; }
    else { u = e - 992; v = u + 32; }
}

__device__ void bitonic2048(unsigned long long* keys) {
    int tid = threadIdx.x;
    for (unsigned k = 2; k <= 2048; k <<= 1)
        for (unsigned j = k >> 1; j > 0; j >>= 1) {
            __syncthreads();
            for (unsigned i = tid; i < 2048; i += 256) {
                unsigned l = i ^ j;
                if (l > i) {
                    unsigned long long a = keys[i], b = keys[l];
                    bool up = ((i & k) == 0);
                    if ((a > b) == up) { keys[i] = b; keys[l] = a; }
                }
            }
        }
    __syncthreads();
}

__device__ __forceinline__ uint32_t smem_u32(const void* p) {
    uint32_t a;
    asm("{ .reg .u64 t; cvta.to.shared.u64 t, %1; cvt.u32.u64 %0, t; }" : "=r"(a) : "l"(p));
    return a;
}
__device__ __forceinline__ void st_cluster_f32(uint32_t addr, int rank, float v) {
    uint32_t r;
    asm volatile("mapa.shared::cluster.u32 %0, %1, %2;" : "=r"(r) : "r"(addr), "r"(rank));
    asm volatile("st.shared::cluster.b32 [%0], %1;" :: "r"(r), "f"(v) : "memory");
}
#define CLUSTER_SYNC() do { \
    asm volatile("barrier.cluster.arrive.aligned;" ::: "memory"); \
    asm volatile("barrier.cluster.wait.aligned;" ::: "memory"); } while (0)

// ---------------- stage 1: softmax + one-hot + pool ----------------
__global__ void pool_kernel(const float* __restrict__ x, const int* __restrict__ y) {
    int idx = blockIdx.x * blockDim.x + threadIdx.x;
    if (idx >= NIMG * NPX) return;
    int m = idx >> 10, cell = idx & 1023;
    int gi = cell >> 5, gj = cell & 31;
    float acc = 0.f;
    if (m < 12) {
        int b = m / 3, c = m % 3 + 1;
        const float* xb = x + (size_t)b * 4 * 65536;
        for (int pi = 0; pi < 8; ++pi) {
            int off0 = (gi * 8 + pi) * 256 + gj * 8;
            #pragma unroll
            for (int pj = 0; pj < 8; ++pj) {
                int off = off0 + pj;
                float x0 = xb[off], x1 = xb[65536 + off],
                      x2 = xb[131072 + off], x3 = xb[196608 + off];
                float mx = fmaxf(fmaxf(x0, x1), fmaxf(x2, x3));
                float e0 = __expf(x0 - mx), e1 = __expf(x1 - mx),
                      e2 = __expf(x2 - mx), e3 = __expf(x3 - mx);
                float ec = (c == 1) ? e1 : ((c == 2) ? e2 : e3);
                acc += ec / (e0 + e1 + e2 + e3);
            }
        }
    } else {
        int mm = m - 12, b = mm / 3, c = mm % 3 + 1;
        const int* yb = y + (size_t)b * 65536;
        int cnt = 0;
        for (int pi = 0; pi < 8; ++pi) {
            int off0 = (gi * 8 + pi) * 256 + gj * 8;
            #pragma unroll
            for (int pj = 0; pj < 8; ++pj) cnt += (yb[off0 + pj] == c);
        }
        acc = (float)cnt;
    }
    g_v[m][cell] = acc * 0.015625f;
}

// ---------------- stage 2: persistence diagrams ----------------
__global__ void diagram_kernel() {
    int m = blockIdx.x >> 1;
    int r = blockIdx.x & 1;
    __shared__ float v[NPX];
    __shared__ unsigned long long keys[2048];
    __shared__ float bArr[2048], dArr[2048];
    __shared__ int parent[NPX];
    __shared__ float r8[8];
    __shared__ int sRu[32], sRv[32];
    __shared__ float sW[32], sBu[32], sBv[32];
    int tid = threadIdx.x;

    for (int i = tid; i < NPX; i += 256) {
        float val = g_v[m][i];
        if (r) val = -val;
        v[i] = val; parent[i] = i;
    }
    __syncthreads();

    for (int e = tid; e < 2048; e += 256) {
        unsigned long long key = ~0ULL;
        if (e < NE) {
            int u, w2; edge_uv(e, u, w2);
            float w = fmaxf(v[u], v[w2]);
            key = ((unsigned long long)ordf(w) << 32) | (unsigned)e;
        }
        keys[e] = key;
    }
    float mn = v[tid], mx = v[tid];
    for (int i = tid + 256; i < NPX; i += 256) { mn = fminf(mn, v[i]); mx = fmaxf(mx, v[i]); }

    bitonic2048(keys);
    float vmax = blkMax(mx, r8);
    float vmin = -blkMax(-mn, r8);

    if (tid < 32) {
        for (int base = 0; base < NE; base += 32) {
            int s = base + tid;
            int e = (int)(unsigned)keys[s];
            int u, vv; edge_uv(e, u, vv);
            float w = fmaxf(v[u], v[vv]);
            int ru = u;
            for (;;) { int p = parent[ru]; if (p == ru) break;
                       int g2 = parent[p]; parent[ru] = g2; ru = g2; }
            int rv = vv;
            for (;;) { int p = parent[rv]; if (p == rv) break;
                       int g2 = parent[p]; parent[rv] = g2; rv = g2; }
            sRu[tid] = ru; sRv[tid] = rv; sW[tid] = w;
            sBu[tid] = v[ru]; sBv[tid] = v[rv];
            __syncwarp();
            if (tid == 0) {
                #pragma unroll 4
                for (int l = 0; l < 32; ++l) {
                    int ra = sRu[l], rb = sRv[l];
                    float ba = sBu[l], bb2 = sBv[l];
                    int pa = parent[ra];
                    int pb2 = parent[rb];
                    if (pa != ra) {
                        do { ra = pa; pa = parent[ra]; } while (pa != ra);
                        ba = v[ra];
                    }
                    if (pb2 != rb) {
                        do { rb = pb2; pb2 = parent[rb]; } while (pb2 != rb);
                        bb2 = v[rb];
                    }
                    float wl = sW[l];
                    float b, d;
                    if (ra == rb) { b = wl; d = wl; }
                    else {
                        b = fmaxf(ba, bb2); d = wl;
                        if (ba <= bb2) parent[rb] = ra;
                        else           parent[ra] = rb;
                    }
                    bArr[base + l] = b; dArr[base + l] = d;
                }
            }
            __syncwarp();
        }
        if (tid == 0 && r == 0) { bArr[NE] = vmin; dArr[NE] = vmax; }
    }
    __syncthreads();

    int limit = (r == 0) ? NE + 1 : NE;
    for (int e = tid; e < 2048; e += 256) {
        unsigned long long key = ~0ULL;
        if (e < limit) {
            float pval = dArr[e] - bArr[e];
            key = ((unsigned long long)(~ordf(pval)) << 32) | (unsigned)e;
        }
        keys[e] = key;
    }
    bitonic2048(keys);

    if (tid < KTOP) {
        int s = (int)(unsigned)keys[tid];
        if (r == 0) {
            g_bd[m][0][0][tid] = bArr[s];
            g_bd[m][0][1][tid] = dArr[s];
        } else {
            g_bd[m][1][0][tid] = -dArr[s];
            g_bd[m][1][1][tid] = -bArr[s];
        }
    }
}

// ---------------- stage 3: factorized clustered Sinkhorn ----------------
// Register-resident E, coalesced DSMEM exchange + barrier.cluster, inlined
// reductions (second barrier doubles as EF/EG visibility), convergence
// early-exit (cluster-consistent: F/G bitwise identical across ranks).
#define OFF_PBF 0                 // [4][256]
#define OFF_PBG 1024
#define OFF_F   2048
#define OFF_G   2304
#define OFF_EXG 2560
#define OFF_EXF 2816
#define OFF_EDA 3072
#define OFF_EDB 3328
#define OFF_DAS 3584
#define OFF_DBS 3840
#define OFF_A   4096              // float2[256]
#define OFF_B   4608
#define OFF_RED 5120              // r8 for K
#define OFF_RED2 5128             // r8 for delta
#define OFF_SC  5136              // [0]=F2 [1]=G2 [2]=EF2 [3]=EG2
#define SINK_SMEM_FLOATS 5140

__global__ void __cluster_dims__(CLU, 1, 1) __launch_bounds__(256, 1)
sinkhorn_kernel(float* __restrict__ out) {
    extern __shared__ float sm[];
    float* pbf = sm + OFF_PBF;
    float* pbg = sm + OFF_PBG;
    float* F = sm + OFF_F;
    float* G = sm + OFF_G;
    float* EG = sm + OFF_EXG;
    float* EF = sm + OFF_EXF;
    float* EDA = sm + OFF_EDA;
    float* EDB = sm + OFF_EDB;
    float* das = sm + OFF_DAS;
    float* dbs = sm + OFF_DBS;
    float2* Ash = (float2*)(sm + OFF_A);
    float2* Bsh = (float2*)(sm + OFF_B);
    float* r8 = sm + OFF_RED;
    float* r8d = sm + OFF_RED2;
    float* sc = sm + OFF_SC;

    int t = threadIdx.x;
    int w = t >> 5;
    int p = blockIdx.x >> 2;
    int q = blockIdx.x & 3;
    int q64 = q * 64;
    int dim = (p < 12) ? 0 : 1;
    int img = (p < 12) ? p : p - 12;

    float ab = g_bd[img][dim][0][t],      ad = g_bd[img][dim][1][t];
    float bb = g_bd[12 + img][dim][0][t], bd = g_bd[12 + img][dim][1][t];
    float2 a = make_float2(ab, ad), b = make_float2(bb, bd);
    Ash[t] = a; Bsh[t] = b;
    float da = 0.5f * (ad - ab), db = 0.5f * (bd - bb);
    F[t] = 0.f; G[t] = 0.f; EG[t] = 1.f;
    if (t < 4) sc[t] = (t < 2) ? 0.f : 1.f;
    __syncthreads();

    float mC = fmaxf(da, db);
    #pragma unroll 4
    for (int i = 0; i < KTOP; ++i) {
        float2 aq = Ash[i];
        mC = fmaxf(mC, fmaxf(fabsf(aq.x - b.x), fabsf(aq.y - b.y)));
    }
    float eps = 0.02f * fmaxf(blkMax(mC, r8), 1e-6f);
    float ie = 1.f / eps;
    das[t] = da * ie; dbs[t] = db * ie;
    EDA[t] = __expf(-da * ie); EDB[t] = __expf(-db * ie);

    float4 rEf[16], rEg[16];
    #pragma unroll
    for (int k = 0; k < 16; ++k) {
        float2 b0 = Bsh[q64 + k * 4 + 0], b1 = Bsh[q64 + k * 4 + 1],
               b2 = Bsh[q64 + k * 4 + 2], b3 = Bsh[q64 + k * 4 + 3];
        rEf[k].x = __expf(-fmaxf(fabsf(a.x - b0.x), fabsf(a.y - b0.y)) * ie);
        rEf[k].y = __expf(-fmaxf(fabsf(a.x - b1.x), fabsf(a.y - b1.y)) * ie);
        rEf[k].z = __expf(-fmaxf(fabsf(a.x - b2.x), fabsf(a.y - b2.y)) * ie);
        rEf[k].w = __expf(-fmaxf(fabsf(a.x - b3.x), fabsf(a.y - b3.y)) * ie);
        float2 a0 = Ash[q64 + k * 4 + 0], a1 = Ash[q64 + k * 4 + 1],
               a2 = Ash[q64 + k * 4 + 2], a3 = Ash[q64 + k * 4 + 3];
        rEg[k].x = __expf(-fmaxf(fabsf(a0.x - b.x), fabsf(a0.y - b.y)) * ie);
        rEg[k].y = __expf(-fmaxf(fabsf(a1.x - b.x), fabsf(a1.y - b.y)) * ie);
        rEg[k].z = __expf(-fmaxf(fabsf(a2.x - b.x), fabsf(a2.y - b.y)) * ie);
        rEg[k].w = __expf(-fmaxf(fabsf(a3.x - b.x), fabsf(a3.y - b.y)) * ie);
    }
    __syncthreads();
    CLUSTER_SYNC();

    uint32_t pbf_addr = smem_u32(&pbf[q * 256 + t]);
    uint32_t pbg_addr = smem_u32(&pbg[q * 256 + t]);
    float K_G = 0.f, K_F;
    float myEDA = EDA[t], myEDB = EDB[t];
    float gOld = 0.f;
    const float4* EGv = (const float4*)(EG + q64);
    const float4* EFv = (const float4*)(EF + q64);

    for (int it = 0; it < SINK_ITERS; ++it) {
        // ---- f half-iter ----
        float4 acc = make_float4(0.f, 0.f, 0.f, 0.f);
        #pragma unroll
        for (int k = 0; k < 16; ++k) {
            float4 g4 = EGv[k];
            acc.x = fmaf(g4.x, rEf[k].x, acc.x);
            acc.y = fmaf(g4.y, rEf[k].y, acc.y);
            acc.z = fmaf(g4.z, rEf[k].z, acc.z);
            acc.w = fmaf(g4.w, rEf[k].w, acc.w);
        }
        float s = (acc.x + acc.y) + (acc.z + acc.w);
        #pragma unroll
        for (int rr = 0; rr < CLU; ++rr) st_cluster_f32(pbf_addr, rr, s);
        if (t < 32) {
            float s2 = 0.f;
            #pragma unroll
            for (int k = 0; k < 8; ++k) { int j = t + k * 32; s2 = fmaf(EG[j], EDB[j], s2); }
            #pragma unroll
            for (int o = 16; o; o >>= 1) s2 += __shfl_xor_sync(0xffffffffu, s2, o);
            if (t == 0) sc[0] = -(K_G + __logf(s2 + 256.f * sc[3]));
        }
        CLUSTER_SYNC();
        float phiF;
        {
            float S = ((pbf[t] + pbf[256 + t]) + (pbf[512 + t] + pbf[768 + t]))
                    + 256.f * sc[3] * myEDA;
            phiF = -(K_G + __logf(S));
            F[t] = phiF;
            float m2 = phiF;
            #pragma unroll
            for (int o = 16; o; o >>= 1) m2 = fmaxf(m2, __shfl_xor_sync(0xffffffffu, m2, o));
            if ((t & 31) == 0) r8[w] = m2;
        }
        __syncthreads();
        {
            K_F = r8[0];
            #pragma unroll
            for (int k = 1; k < 8; ++k) K_F = fmaxf(K_F, r8[k]);
            EF[t] = __expf(phiF - K_F);
            if (t == 0) sc[2] = __expf(sc[0] - K_F);
        }
        __syncthreads();        // EF visible; r8 free

        // ---- g half-iter ----
        acc = make_float4(0.f, 0.f, 0.f, 0.f);
        #pragma unroll
        for (int k = 0; k < 16; ++k) {
            float4 f4 = EFv[k];
            acc.x = fmaf(f4.x, rEg[k].x, acc.x);
            acc.y = fmaf(f4.y, rEg[k].y, acc.y);
            acc.z = fmaf(f4.z, rEg[k].z, acc.z);
            acc.w = fmaf(f4.w, rEg[k].w, acc.w);
        }
        s = (acc.x + acc.y) + (acc.z + acc.w);
        #pragma unroll
        for (int rr = 0; rr < CLU; ++rr) st_cluster_f32(pbg_addr, rr, s);
        if (t < 32) {
            float s2 = 0.f;
            #pragma unroll
            for (int k = 0; k < 8; ++k) { int i = t + k * 32; s2 = fmaf(EF[i], EDA[i], s2); }
            #pragma unroll
            for (int o = 16; o; o >>= 1) s2 += __shfl_xor_sync(0xffffffffu, s2, o);
            if (t == 0) sc[1] = -(K_F + __logf(s2 + 256.f * sc[2]));
        }
        CLUSTER_SYNC();
        float phiG;
        {
            float S = ((pbg[t] + pbg[256 + t]) + (pbg[512 + t] + pbg[768 + t]))
                    + 256.f * sc[2] * myEDB;
            phiG = -(K_F + __logf(S));
            G[t] = phiG;
            float dlt = fabsf(phiG - gOld);
            gOld = phiG;
            float m2 = phiG;
            #pragma unroll
            for (int o = 16; o; o >>= 1) {
                m2 = fmaxf(m2, __shfl_xor_sync(0xffffffffu, m2, o));
                dlt = fmaxf(dlt, __shfl_xor_sync(0xffffffffu, dlt, o));
            }
            if ((t & 31) == 0) { r8[w] = m2; r8d[w] = dlt; }
        }
        __syncthreads();
        float maxd;
        {
            K_G = r8[0]; maxd = r8d[0];
            #pragma unroll
            for (int k = 1; k < 8; ++k) {
                K_G = fmaxf(K_G, r8[k]);
                maxd = fmaxf(maxd, r8d[k]);
            }
            EG[t] = __expf(phiG - K_G);
            if (t == 0) sc[3] = __expf(sc[1] - K_G);
        }
        __syncthreads();        // EG visible; r8 free
        if (it >= MIN_ITERS && maxd < EXIT_TOL) break;   // identical on all ranks
    }

    // ---- final cost partial ----
    float acc2 = 0.f;
    float myG = G[t];
    #pragma unroll 4
    for (int ii = 0; ii < 64; ++ii) {
        float2 aq = Ash[q64 + ii];
        float cs = fmaxf(fabsf(aq.x - b.x), fabsf(aq.y - b.y)) * ie;
        acc2 += __expf(F[q64 + ii] + myG - cs) * cs;
    }
    if (t < 64) {
        int i = q64 + t;
        acc2 += 256.f * __expf(F[i] + sc[1] - das[i]) * das[i];
        acc2 += 256.f * __expf(sc[0] + G[i] - dbs[i]) * dbs[i];
    }
    float tot = blkSum(acc2, r8);

    if (t == 0) {
        g_wpart[p * CLU + q] = tot * eps;
        __threadfence();
        int ticket = atomicAdd(&g_ctr, 1);
        if (ticket == NIMG * CLU - 1) {
            g_ctr = 0;
            float ssum = 0.f;
            for (int pp = 0; pp < NIMG; ++pp) {
                float w2 = 0.f;
                for (int qq = 0; qq < CLU; ++qq) w2 += g_wpart[pp * CLU + qq];
                ssum += w2;
            }
            out[0] = ssum * 0.25f;
        }
    }
}

extern "C" void kernel_launch(void* const* d_in, const int* in_sizes, int n_in,
                              void* d_out, int out_size) {
    (void)in_sizes; (void)n_in; (void)out_size;
    const float* x = (const float*)d_in[0];
    const int* y = (const int*)d_in[1];
    static bool attr_set = false;
    if (!attr_set) {
        cudaFuncSetAttribute(sinkhorn_kernel,
                             cudaFuncAttributeMaxDynamicSharedMemorySize,
                             SINK_SMEM_FLOATS * 4);
        attr_set = true;
    }
    pool_kernel<<<(NIMG * NPX + 255) / 256, 256>>>(x, y);
    diagram_kernel<<<48, 256>>>();
    sinkhorn_kernel<<<NIMG * CLU, 256, SINK_SMEM_FLOATS * 4>>>((float*)d_out);
}

// round 11
// speedup vs baseline: 1.6037x; 1.0011x over previous
#include <cuda_runtime.h>
#include <cuda_bf16.h>
#include <cstdint>

#define NPX 1024
#define NE 1984
#define KTOP 256
#define NIMG 24
#define SINK_ITERS 150
#define CLU 4
#define EXIT_TOL 1e-3f
#define MIN_ITERS 20

__device__ float g_v[NIMG][NPX];
__device__ float g_bd[NIMG][2][2][KTOP];
__device__ float g_wpart[NIMG * CLU];
__device__ int g_ctr;

__device__ __forceinline__ unsigned ordf(float f) {
    unsigned u = __float_as_uint(f);
    return (u & 0x80000000u) ? ~u : (u | 0x80000000u);
}

__device__ __forceinline__ float blkMax(float v, float* r8) {
    #pragma unroll
    for (int o = 16; o; o >>= 1) v = fmaxf(v, __shfl_xor_sync(0xffffffffu, v, o));
    if ((threadIdx.x & 31) == 0) r8[threadIdx.x >> 5] = v;
    __syncthreads();
    float m = r8[0];
    #pragma unroll
    for (int k = 1; k < 8; ++k) m = fmaxf(m, r8[k]);
    __syncthreads();
    return m;
}
__device__ __forceinline__ float blkSum(float v, float* r8) {
    #pragma unroll
    for (int o = 16; o; o >>= 1) v += __shfl_xor_sync(0xffffffffu, v, o);
    if ((threadIdx.x & 31) == 0) r8[threadIdx.x >> 5] = v;
    __syncthreads();
    float s = r8[0];
    #pragma unroll
    for (int k = 1; k < 8; ++k) s += r8[k];
    __syncthreads();
    return s;
}

__device__ __forceinline__ void edge_uv(int e, int& u, int& v) {
    if (e < 992) { int rr = e / 31, cc = e - rr * 31; u = rr * 32 + cc; v = u + 1; }
    else { u = e - 992; v = u + 32; }
}

__device__ void bitonic2048(unsigned long long* keys) {
    int tid = threadIdx.x;
    for (unsigned k = 2; k <= 2048; k <<= 1)
        for (unsigned j = k >> 1; j > 0; j >>= 1) {
            __syncthreads();
            for (unsigned i = tid; i < 2048; i += 256) {
                unsigned l = i ^ j;
                if (l > i) {
                    unsigned long long a = keys[i], b = keys[l];
                    bool up = ((i & k) == 0);
                    if ((a > b) == up) { keys[i] = b; keys[l] = a; }
                }
            }
        }
    __syncthreads();
}

__device__ __forceinline__ uint32_t smem_u32(const void* p) {
    uint32_t a;
    asm("{ .reg .u64 t; cvta.to.shared.u64 t, %1; cvt.u32.u64 %0, t; }" : "=r"(a) : "l"(p));
    return a;
}
__device__ __forceinline__ void st_cluster_f32(uint32_t addr, int rank, float v) {
    uint32_t r;
    asm volatile("mapa.shared::cluster.u32 %0, %1, %2;" : "=r"(r) : "r"(addr), "r"(rank));
    asm volatile("st.shared::cluster.b32 [%0], %1;" :: "r"(r), "f"(v) : "memory");
}
#define CLUSTER_SYNC() do { \
    asm volatile("barrier.cluster.arrive.aligned;" ::: "memory"); \
    asm volatile("barrier.cluster.wait.aligned;" ::: "memory"); } while (0)

// ---------------- stage 1: softmax + one-hot + pool ----------------
__global__ void pool_kernel(const float* __restrict__ x, const int* __restrict__ y) {
    int idx = blockIdx.x * blockDim.x + threadIdx.x;
    if (idx >= NIMG * NPX) return;
    int m = idx >> 10, cell = idx & 1023;
    int gi = cell >> 5, gj = cell & 31;
    float acc = 0.f;
    if (m < 12) {
        int b = m / 3, c = m % 3 + 1;
        const float* xb = x + (size_t)b * 4 * 65536;
        for (int pi = 0; pi < 8; ++pi) {
            int off0 = (gi * 8 + pi) * 256 + gj * 8;
            #pragma unroll
            for (int pj = 0; pj < 8; ++pj) {
                int off = off0 + pj;
                float x0 = xb[off], x1 = xb[65536 + off],
                      x2 = xb[131072 + off], x3 = xb[196608 + off];
                float mx = fmaxf(fmaxf(x0, x1), fmaxf(x2, x3));
                float e0 = __expf(x0 - mx), e1 = __expf(x1 - mx),
                      e2 = __expf(x2 - mx), e3 = __expf(x3 - mx);
                float ec = (c == 1) ? e1 : ((c == 2) ? e2 : e3);
                acc += ec / (e0 + e1 + e2 + e3);
            }
        }
    } else {
        int mm = m - 12, b = mm / 3, c = mm % 3 + 1;
        const int* yb = y + (size_t)b * 65536;
        int cnt = 0;
        for (int pi = 0; pi < 8; ++pi) {
            int off0 = (gi * 8 + pi) * 256 + gj * 8;
            #pragma unroll
            for (int pj = 0; pj < 8; ++pj) cnt += (yb[off0 + pj] == c);
        }
        acc = (float)cnt;
    }
    g_v[m][cell] = acc * 0.015625f;
}

// ---------------- stage 2: persistence diagrams ----------------
__global__ void diagram_kernel() {
    int m = blockIdx.x >> 1;
    int r = blockIdx.x & 1;
    __shared__ float v[NPX];
    __shared__ unsigned long long keys[2048];
    __shared__ float bArr[2048], dArr[2048];
    __shared__ int parent[NPX];
    __shared__ float r8[8];
    __shared__ int sRu[32], sRv[32];
    __shared__ float sW[32], sBu[32], sBv[32];
    int tid = threadIdx.x;

    for (int i = tid; i < NPX; i += 256) {
        float val = g_v[m][i];
        if (r) val = -val;
        v[i] = val; parent[i] = i;
    }
    __syncthreads();

    for (int e = tid; e < 2048; e += 256) {
        unsigned long long key = ~0ULL;
        if (e < NE) {
            int u, w2; edge_uv(e, u, w2);
            float w = fmaxf(v[u], v[w2]);
            key = ((unsigned long long)ordf(w) << 32) | (unsigned)e;
        }
        keys[e] = key;
    }
    float mn = v[tid], mx = v[tid];
    for (int i = tid + 256; i < NPX; i += 256) { mn = fminf(mn, v[i]); mx = fmaxf(mx, v[i]); }

    bitonic2048(keys);
    float vmax = blkMax(mx, r8);
    float vmin = -blkMax(-mn, r8);

    if (tid < 32) {
        for (int base = 0; base < NE; base += 32) {
            int s = base + tid;
            int e = (int)(unsigned)keys[s];
            int u, vv; edge_uv(e, u, vv);
            float w = fmaxf(v[u], v[vv]);
            int ru = u;
            for (;;) { int p = parent[ru]; if (p == ru) break;
                       int g2 = parent[p]; parent[ru] = g2; ru = g2; }
            int rv = vv;
            for (;;) { int p = parent[rv]; if (p == rv) break;
                       int g2 = parent[p]; parent[rv] = g2; rv = g2; }
            sRu[tid] = ru; sRv[tid] = rv; sW[tid] = w;
            sBu[tid] = v[ru]; sBv[tid] = v[rv];
            __syncwarp();
            if (tid == 0) {
                #pragma unroll 4
                for (int l = 0; l < 32; ++l) {
                    int ra = sRu[l], rb = sRv[l];
                    float ba = sBu[l], bb2 = sBv[l];
                    int pa = parent[ra];
                    int pb2 = parent[rb];
                    if (pa != ra) {
                        do { ra = pa; pa = parent[ra]; } while (pa != ra);
                        ba = v[ra];
                    }
                    if (pb2 != rb) {
                        do { rb = pb2; pb2 = parent[rb]; } while (pb2 != rb);
                        bb2 = v[rb];
                    }
                    float wl = sW[l];
                    float b, d;
                    if (ra == rb) { b = wl; d = wl; }
                    else {
                        b = fmaxf(ba, bb2); d = wl;
                        if (ba <= bb2) parent[rb] = ra;
                        else           parent[ra] = rb;
                    }
                    bArr[base + l] = b; dArr[base + l] = d;
                }
            }
            __syncwarp();
        }
        if (tid == 0 && r == 0) { bArr[NE] = vmin; dArr[NE] = vmax; }
    }
    __syncthreads();

    int limit = (r == 0) ? NE + 1 : NE;
    for (int e = tid; e < 2048; e += 256) {
        unsigned long long key = ~0ULL;
        if (e < limit) {
            float pval = dArr[e] - bArr[e];
            key = ((unsigned long long)(~ordf(pval)) << 32) | (unsigned)e;
        }
        keys[e] = key;
    }
    bitonic2048(keys);

    if (tid < KTOP) {
        int s = (int)(unsigned)keys[tid];
        if (r == 0) {
            g_bd[m][0][0][tid] = bArr[s];
            g_bd[m][0][1][tid] = dArr[s];
        } else {
            g_bd[m][1][0][tid] = -dArr[s];
            g_bd[m][1][1][tid] = -bArr[s];
        }
    }
}

// ---------------- stage 3: factorized clustered Sinkhorn ----------------
#define OFF_PBF 0                 // [4][256]
#define OFF_PBG 1024
#define OFF_F   2048
#define OFF_G   2304
#define OFF_EXG 2560
#define OFF_EXF 2816
#define OFF_EDA 3072
#define OFF_EDB 3328
#define OFF_DAS 3584
#define OFF_DBS 3840
#define OFF_A   4096              // float2[256]
#define OFF_B   4608
#define OFF_RED 5120
#define OFF_RED2 5128
#define OFF_SC  5136              // [0]=F2 [1]=G2 [2]=EF2 [3]=EG2
#define SINK_SMEM_FLOATS 5140

__global__ void __cluster_dims__(CLU, 1, 1) __launch_bounds__(256, 1)
sinkhorn_kernel(float* __restrict__ out) {
    extern __shared__ float sm[];
    float* pbf = sm + OFF_PBF;
    float* pbg = sm + OFF_PBG;
    float* F = sm + OFF_F;
    float* G = sm + OFF_G;
    float* EG = sm + OFF_EXG;
    float* EF = sm + OFF_EXF;
    float* EDA = sm + OFF_EDA;
    float* EDB = sm + OFF_EDB;
    float* das = sm + OFF_DAS;
    float* dbs = sm + OFF_DBS;
    float2* Ash = (float2*)(sm + OFF_A);
    float2* Bsh = (float2*)(sm + OFF_B);
    float* r8 = sm + OFF_RED;
    float* r8d = sm + OFF_RED2;
    float* sc = sm + OFF_SC;

    int t = threadIdx.x;
    int w = t >> 5;
    int p = blockIdx.x >> 2;
    int q = blockIdx.x & 3;
    int q64 = q * 64;
    int dim = (p < 12) ? 0 : 1;
    int img = (p < 12) ? p : p - 12;

    float ab = g_bd[img][dim][0][t],      ad = g_bd[img][dim][1][t];
    float bb = g_bd[12 + img][dim][0][t], bd = g_bd[12 + img][dim][1][t];
    float2 a = make_float2(ab, ad), b = make_float2(bb, bd);
    Ash[t] = a; Bsh[t] = b;
    float da = 0.5f * (ad - ab), db = 0.5f * (bd - bb);
    F[t] = 0.f; G[t] = 0.f; EG[t] = 1.f;
    if (t < 4) sc[t] = (t < 2) ? 0.f : 1.f;
    __syncthreads();

    float mC = fmaxf(da, db);
    #pragma unroll 4
    for (int i = 0; i < KTOP; ++i) {
        float2 aq = Ash[i];
        mC = fmaxf(mC, fmaxf(fabsf(aq.x - b.x), fabsf(aq.y - b.y)));
    }
    float eps = 0.02f * fmaxf(blkMax(mC, r8), 1e-6f);
    float ie = 1.f / eps;
    das[t] = da * ie; dbs[t] = db * ie;
    EDA[t] = __expf(-da * ie); EDB[t] = __expf(-db * ie);

    float4 rEf[16], rEg[16];
    #pragma unroll
    for (int k = 0; k < 16; ++k) {
        float2 b0 = Bsh[q64 + k * 4 + 0], b1 = Bsh[q64 + k * 4 + 1],
               b2 = Bsh[q64 + k * 4 + 2], b3 = Bsh[q64 + k * 4 + 3];
        rEf[k].x = __expf(-fmaxf(fabsf(a.x - b0.x), fabsf(a.y - b0.y)) * ie);
        rEf[k].y = __expf(-fmaxf(fabsf(a.x - b1.x), fabsf(a.y - b1.y)) * ie);
        rEf[k].z = __expf(-fmaxf(fabsf(a.x - b2.x), fabsf(a.y - b2.y)) * ie);
        rEf[k].w = __expf(-fmaxf(fabsf(a.x - b3.x), fabsf(a.y - b3.y)) * ie);
        float2 a0 = Ash[q64 + k * 4 + 0], a1 = Ash[q64 + k * 4 + 1],
               a2 = Ash[q64 + k * 4 + 2], a3 = Ash[q64 + k * 4 + 3];
        rEg[k].x = __expf(-fmaxf(fabsf(a0.x - b.x), fabsf(a0.y - b.y)) * ie);
        rEg[k].y = __expf(-fmaxf(fabsf(a1.x - b.x), fabsf(a1.y - b.y)) * ie);
        rEg[k].z = __expf(-fmaxf(fabsf(a2.x - b.x), fabsf(a2.y - b.y)) * ie);
        rEg[k].w = __expf(-fmaxf(fabsf(a3.x - b.x), fabsf(a3.y - b.y)) * ie);
    }
    __syncthreads();
    CLUSTER_SYNC();

    uint32_t pbf_addr = smem_u32(&pbf[q * 256 + t]);
    uint32_t pbg_addr = smem_u32(&pbg[q * 256 + t]);
    float K_G = 0.f, K_F;
    float myEDA = EDA[t], myEDB = EDB[t];
    float gOld = 0.f;
    const float4* EGv = (const float4*)(EG + q64);
    const float4* EFv = (const float4*)(EF + q64);

    for (int it = 0; it < SINK_ITERS; ++it) {
        // ---- f half-iter ----
        float4 acc = make_float4(0.f, 0.f, 0.f, 0.f);
        #pragma unroll
        for (int k = 0; k < 16; ++k) {
            float4 g4 = EGv[k];
            acc.x = fmaf(g4.x, rEf[k].x, acc.x);
            acc.y = fmaf(g4.y, rEf[k].y, acc.y);
            acc.z = fmaf(g4.z, rEf[k].z, acc.z);
            acc.w = fmaf(g4.w, rEf[k].w, acc.w);
        }
        float s = (acc.x + acc.y) + (acc.z + acc.w);
        #pragma unroll
        for (int rr = 0; rr < CLU; ++rr) st_cluster_f32(pbf_addr, rr, s);
        if (t < 32) {
            float s2 = 0.f;
            #pragma unroll
            for (int k = 0; k < 8; ++k) { int j = t + k * 32; s2 = fmaf(EG[j], EDB[j], s2); }
            #pragma unroll
            for (int o = 16; o; o >>= 1) s2 += __shfl_xor_sync(0xffffffffu, s2, o);
            if (t == 0) sc[0] = -(K_G + __logf(s2 + 256.f * sc[3]));
        }
        CLUSTER_SYNC();
        float phiF;
        {
            float S = ((pbf[t] + pbf[256 + t]) + (pbf[512 + t] + pbf[768 + t]))
                    + 256.f * sc[3] * myEDA;
            phiF = -(K_G + __logf(S));
            F[t] = phiF;
            float m2 = phiF;
            #pragma unroll
            for (int o = 16; o; o >>= 1) m2 = fmaxf(m2, __shfl_xor_sync(0xffffffffu, m2, o));
            if ((t & 31) == 0) r8[w] = m2;
        }
        __syncthreads();
        {
            K_F = r8[0];
            #pragma unroll
            for (int k = 1; k < 8; ++k) K_F = fmaxf(K_F, r8[k]);
            EF[t] = __expf(phiF - K_F);
            if (t == 0) sc[2] = __expf(sc[0] - K_F);
        }
        __syncthreads();

        // ---- g half-iter ----
        acc = make_float4(0.f, 0.f, 0.f, 0.f);
        #pragma unroll
        for (int k = 0; k < 16; ++k) {
            float4 f4 = EFv[k];
            acc.x = fmaf(f4.x, rEg[k].x, acc.x);
            acc.y = fmaf(f4.y, rEg[k].y, acc.y);
            acc.z = fmaf(f4.z, rEg[k].z, acc.z);
            acc.w = fmaf(f4.w, rEg[k].w, acc.w);
        }
        s = (acc.x + acc.y) + (acc.z + acc.w);
        #pragma unroll
        for (int rr = 0; rr < CLU; ++rr) st_cluster_f32(pbg_addr, rr, s);
        if (t < 32) {
            float s2 = 0.f;
            #pragma unroll
            for (int k = 0; k < 8; ++k) { int i = t + k * 32; s2 = fmaf(EF[i], EDA[i], s2); }
            #pragma unroll
            for (int o = 16; o; o >>= 1) s2 += __shfl_xor_sync(0xffffffffu, s2, o);
            if (t == 0) sc[1] = -(K_F + __logf(s2 + 256.f * sc[2]));
        }
        CLUSTER_SYNC();
        float phiG;
        {
            float S = ((pbg[t] + pbg[256 + t]) + (pbg[512 + t] + pbg[768 + t]))
                    + 256.f * sc[2] * myEDB;
            phiG = -(K_F + __logf(S));
            G[t] = phiG;
            float dlt = fabsf(phiG - gOld);
            gOld = phiG;
            float m2 = phiG;
            #pragma unroll
            for (int o = 16; o; o >>= 1) {
                m2 = fmaxf(m2, __shfl_xor_sync(0xffffffffu, m2, o));
                dlt = fmaxf(dlt, __shfl_xor_sync(0xffffffffu, dlt, o));
            }
            if ((t & 31) == 0) { r8[w] = m2; r8d[w] = dlt; }
        }
        __syncthreads();
        float maxd;
        {
            K_G = r8[0]; maxd = r8d[0];
            #pragma unroll
            for (int k = 1; k < 8; ++k) {
                K_G = fmaxf(K_G, r8[k]);
                maxd = fmaxf(maxd, r8d[k]);
            }
            EG[t] = __expf(phiG - K_G);
            if (t == 0) sc[3] = __expf(sc[1] - K_G);
        }
        __syncthreads();
        if (it >= MIN_ITERS && maxd < EXIT_TOL) break;   // identical on all ranks
    }

    // ---- final cost partial ----
    float acc2 = 0.f;
    float myG = G[t];
    #pragma unroll 4
    for (int ii = 0; ii < 64; ++ii) {
        float2 aq = Ash[q64 + ii];
        float cs = fmaxf(fabsf(aq.x - b.x), fabsf(aq.y - b.y)) * ie;
        acc2 += __expf(F[q64 + ii] + myG - cs) * cs;
    }
    if (t < 64) {
        int i = q64 + t;
        acc2 += 256.f * __expf(F[i] + sc[1] - das[i]) * das[i];
        acc2 += 256.f * __expf(sc[0] + G[i] - dbs[i]) * dbs[i];
    }
    float tot = blkSum(acc2, r8);

    if (t == 0) {
        g_wpart[p * CLU + q] = tot * eps;
        __threadfence();
        int ticket = atomicAdd(&g_ctr, 1);
        if (ticket == NIMG * CLU - 1) {
            g_ctr = 0;
            float ssum = 0.f;
            for (int pp = 0; pp < NIMG; ++pp) {
                float w2 = 0.f;
                for (int qq = 0; qq < CLU; ++qq) w2 += g_wpart[pp * CLU + qq];
                ssum += w2;
            }
            out[0] = ssum * 0.25f;
        }
    }
}

extern "C" void kernel_launch(void* const* d_in, const int* in_sizes, int n_in,
                              void* d_out, int out_size) {
    (void)in_sizes; (void)n_in; (void)out_size;
    const float* x = (const float*)d_in[0];
    const int* y = (const int*)d_in[1];
    static bool attr_set = false;
    if (!attr_set) {
        cudaFuncSetAttribute(sinkhorn_kernel,
                             cudaFuncAttributeMaxDynamicSharedMemorySize,
                             SINK_SMEM_FLOATS * 4);
        attr_set = true;
    }
    pool_kernel<<<(NIMG * NPX + 255) / 256, 256>>>(x, y);
    diagram_kernel<<<48, 256>>>();
    sinkhorn_kernel<<<NIMG * CLU, 256, SINK_SMEM_FLOATS * 4>>>((float*)d_out);
}

// round 12
// speedup vs baseline: 1.6321x; 1.0177x over previous
#include <cuda_runtime.h>
#include <cuda_bf16.h>
#include <cstdint>

#define NPX 1024
#define NE 1984
#define KTOP 256
#define NIMG 24
#define SINK_ITERS 150
#define CLU 4
#define EXIT_TOL 1e-3f
#define MIN_ITERS 20

__device__ float g_v[NIMG][NPX];
__device__ float g_bd[NIMG][2][2][KTOP];
__device__ float g_wpart[NIMG * CLU];
__device__ int g_ctr;

__device__ __forceinline__ unsigned ordf(float f) {
    unsigned u = __float_as_uint(f);
    return (u & 0x80000000u) ? ~u : (u | 0x80000000u);
}

__device__ __forceinline__ float blkMax(float v, float* r8) {
    #pragma unroll
    for (int o = 16; o; o >>= 1) v = fmaxf(v, __shfl_xor_sync(0xffffffffu, v, o));
    if ((threadIdx.x & 31) == 0) r8[threadIdx.x >> 5] = v;
    __syncthreads();
    float m = r8[0];
    #pragma unroll
    for (int k = 1; k < 8; ++k) m = fmaxf(m, r8[k]);
    __syncthreads();
    return m;
}
__device__ __forceinline__ float blkSum(float v, float* r8) {
    #pragma unroll
    for (int o = 16; o; o >>= 1) v += __shfl_xor_sync(0xffffffffu, v, o);
    if ((threadIdx.x & 31) == 0) r8[threadIdx.x >> 5] = v;
    __syncthreads();
    float s = r8[0];
    #pragma unroll
    for (int k = 1; k < 8; ++k) s += r8[k];
    __syncthreads();
    return s;
}

__device__ __forceinline__ void edge_uv(int e, int& u, int& v) {
    if (e < 992) { int rr = e / 31, cc = e - rr * 31; u = rr * 32 + cc; v = u + 1; }
    else { u = e - 992; v = u + 32; }
}

__device__ void bitonic2048(unsigned long long* keys) {
    int tid = threadIdx.x;
    for (unsigned k = 2; k <= 2048; k <<= 1)
        for (unsigned j = k >> 1; j > 0; j >>= 1) {
            __syncthreads();
            for (unsigned i = tid; i < 2048; i += 256) {
                unsigned l = i ^ j;
                if (l > i) {
                    unsigned long long a = keys[i], b = keys[l];
                    bool up = ((i & k) == 0);
                    if ((a > b) == up) { keys[i] = b; keys[l] = a; }
                }
            }
        }
    __syncthreads();
}

__device__ __forceinline__ uint32_t smem_u32(const void* p) {
    uint32_t a;
    asm("{ .reg .u64 t; cvta.to.shared.u64 t, %1; cvt.u32.u64 %0, t; }" : "=r"(a) : "l"(p));
    return a;
}
__device__ __forceinline__ void st_cluster_f32(uint32_t addr, int rank, float v) {
    uint32_t r;
    asm volatile("mapa.shared::cluster.u32 %0, %1, %2;" : "=r"(r) : "r"(addr), "r"(rank));
    asm volatile("st.shared::cluster.b32 [%0], %1;" :: "r"(r), "f"(v) : "memory");
}
#define CLUSTER_SYNC() do { \
    asm volatile("barrier.cluster.arrive.aligned;" ::: "memory"); \
    asm volatile("barrier.cluster.wait.aligned;" ::: "memory"); } while (0)

// ---------------- stage 1: softmax + one-hot + pool (float4 loads) ----------------
__global__ void pool_kernel(const float* __restrict__ x, const int* __restrict__ y) {
    int idx = blockIdx.x * blockDim.x + threadIdx.x;
    if (idx >= NIMG * NPX) return;
    int m = idx >> 10, cell = idx & 1023;
    int gi = cell >> 5, gj = cell & 31;
    float acc = 0.f;
    if (m < 12) {
        int b = m / 3, c = m % 3 + 1;
        const float* xb = x + (size_t)b * 4 * 65536;
        for (int pi = 0; pi < 8; ++pi) {
            int off0 = (gi * 8 + pi) * 256 + gj * 8;
            #pragma unroll
            for (int h = 0; h < 2; ++h) {
                int off = off0 + h * 4;
                float4 v0 = *(const float4*)(xb + off);
                float4 v1 = *(const float4*)(xb + 65536 + off);
                float4 v2 = *(const float4*)(xb + 131072 + off);
                float4 v3 = *(const float4*)(xb + 196608 + off);
                const float* p0 = &v0.x; const float* p1 = &v1.x;
                const float* p2 = &v2.x; const float* p3 = &v3.x;
                #pragma unroll
                for (int j = 0; j < 4; ++j) {
                    float x0 = p0[j], x1 = p1[j], x2 = p2[j], x3 = p3[j];
                    float mx = fmaxf(fmaxf(x0, x1), fmaxf(x2, x3));
                    float e0 = __expf(x0 - mx), e1 = __expf(x1 - mx),
                          e2 = __expf(x2 - mx), e3 = __expf(x3 - mx);
                    float ec = (c == 1) ? e1 : ((c == 2) ? e2 : e3);
                    acc += ec / (e0 + e1 + e2 + e3);
                }
            }
        }
    } else {
        int mm = m - 12, b = mm / 3, c = mm % 3 + 1;
        const int* yb = y + (size_t)b * 65536;
        int cnt = 0;
        for (int pi = 0; pi < 8; ++pi) {
            int off0 = (gi * 8 + pi) * 256 + gj * 8;
            #pragma unroll
            for (int h = 0; h < 2; ++h) {
                int4 yv = *(const int4*)(yb + off0 + h * 4);
                cnt += (yv.x == c) + (yv.y == c) + (yv.z == c) + (yv.w == c);
            }
        }
        acc = (float)cnt;
    }
    g_v[m][cell] = acc * 0.015625f;
}

// ---------------- stage 2: persistence diagrams ----------------
__global__ void diagram_kernel() {
    int m = blockIdx.x >> 1;
    int r = blockIdx.x & 1;
    __shared__ float v[NPX];
    __shared__ unsigned long long keys[2048];
    __shared__ float bArr[2048], dArr[2048];
    __shared__ int parent[NPX];
    __shared__ float r8[8];
    __shared__ int2 sR[32];      // (ru, rv)
    __shared__ float2 sB[32];    // (birth_u, birth_v)
    __shared__ float sW[32];
    int tid = threadIdx.x;

    for (int i = tid; i < NPX; i += 256) {
        float val = g_v[m][i];
        if (r) val = -val;
        v[i] = val; parent[i] = i;
    }
    __syncthreads();

    for (int e = tid; e < 2048; e += 256) {
        unsigned long long key = ~0ULL;
        if (e < NE) {
            int u, w2; edge_uv(e, u, w2);
            float w = fmaxf(v[u], v[w2]);
            key = ((unsigned long long)ordf(w) << 32) | (unsigned)e;
        }
        keys[e] = key;
    }
    float mn = v[tid], mx = v[tid];
    for (int i = tid + 256; i < NPX; i += 256) { mn = fminf(mn, v[i]); mx = fmaxf(mx, v[i]); }

    bitonic2048(keys);
    float vmax = blkMax(mx, r8);
    float vmin = -blkMax(-mn, r8);

    // warp-assisted exact Kruskal. Trivial edges (same root at pre-find)
    // stay trivial (components only merge) -> zero-LDS commit.
    if (tid < 32) {
        for (int base = 0; base < NE; base += 32) {     // NE = 62*32
            int s = base + tid;
            int e = (int)(unsigned)keys[s];
            int u, vv; edge_uv(e, u, vv);
            float w = fmaxf(v[u], v[vv]);
            int ru = u;
            for (;;) { int p = parent[ru]; if (p == ru) break;
                       int g2 = parent[p]; parent[ru] = g2; ru = g2; }
            int rv = vv;
            for (;;) { int p = parent[rv]; if (p == rv) break;
                       int g2 = parent[p]; parent[rv] = g2; rv = g2; }
            sR[tid] = make_int2(ru, rv);
            sB[tid] = make_float2(v[ru], v[rv]);
            sW[tid] = w;
            __syncwarp();
            if (tid == 0) {
                #pragma unroll 4
                for (int l = 0; l < 32; ++l) {
                    int2 rr2 = sR[l];
                    float wl = sW[l];
                    float b, d;
                    if (rr2.x == rr2.y) { b = wl; d = wl; }
                    else {
                        int ra = rr2.x, rb = rr2.y;
                        float2 bb0 = sB[l];
                        float ba = bb0.x, bb2 = bb0.y;
                        int pa = parent[ra];
                        int pb2 = parent[rb];
                        if (pa != ra) {
                            do { ra = pa; pa = parent[ra]; } while (pa != ra);
                            ba = v[ra];
                        }
                        if (pb2 != rb) {
                            do { rb = pb2; pb2 = parent[rb]; } while (pb2 != rb);
                            bb2 = v[rb];
                        }
                        if (ra == rb) { b = wl; d = wl; }
                        else {
                            b = fmaxf(ba, bb2); d = wl;
                            if (ba <= bb2) parent[rb] = ra;
                            else           parent[ra] = rb;
                        }
                    }
                    bArr[base + l] = b; dArr[base + l] = d;
                }
            }
            __syncwarp();
        }
        if (tid == 0 && r == 0) { bArr[NE] = vmin; dArr[NE] = vmax; }
    }
    __syncthreads();

    int limit = (r == 0) ? NE + 1 : NE;
    for (int e = tid; e < 2048; e += 256) {
        unsigned long long key = ~0ULL;
        if (e < limit) {
            float pval = dArr[e] - bArr[e];
            key = ((unsigned long long)(~ordf(pval)) << 32) | (unsigned)e;
        }
        keys[e] = key;
    }
    bitonic2048(keys);

    if (tid < KTOP) {
        int s = (int)(unsigned)keys[tid];
        if (r == 0) {
            g_bd[m][0][0][tid] = bArr[s];
            g_bd[m][0][1][tid] = dArr[s];
        } else {
            g_bd[m][1][0][tid] = -dArr[s];
            g_bd[m][1][1][tid] = -bArr[s];
        }
    }
}

// ---------------- stage 3: factorized clustered Sinkhorn ----------------
// Register-resident E; stale-K (recompute shift/exit every 4 iters — exact
// algebra, any consistent K works; |phi|<=50 keeps exp in range).
#define OFF_PBF 0                 // [4][256]
#define OFF_PBG 1024
#define OFF_F   2048
#define OFF_G   2304
#define OFF_EXG 2560
#define OFF_EXF 2816
#define OFF_EDA 3072
#define OFF_EDB 3328
#define OFF_DAS 3584
#define OFF_DBS 3840
#define OFF_A   4096              // float2[256]
#define OFF_B   4608
#define OFF_RED 5120
#define OFF_RED2 5128
#define OFF_SC  5136              // [0]=F2 [1]=G2 [2]=EF2 [3]=EG2
#define SINK_SMEM_FLOATS 5140

__global__ void __cluster_dims__(CLU, 1, 1) __launch_bounds__(256, 1)
sinkhorn_kernel(float* __restrict__ out) {
    extern __shared__ float sm[];
    float* pbf = sm + OFF_PBF;
    float* pbg = sm + OFF_PBG;
    float* F = sm + OFF_F;
    float* G = sm + OFF_G;
    float* EG = sm + OFF_EXG;
    float* EF = sm + OFF_EXF;
    float* EDA = sm + OFF_EDA;
    float* EDB = sm + OFF_EDB;
    float* das = sm + OFF_DAS;
    float* dbs = sm + OFF_DBS;
    float2* Ash = (float2*)(sm + OFF_A);
    float2* Bsh = (float2*)(sm + OFF_B);
    float* r8 = sm + OFF_RED;
    float* r8d = sm + OFF_RED2;
    float* sc = sm + OFF_SC;

    int t = threadIdx.x;
    int w = t >> 5;
    int p = blockIdx.x >> 2;
    int q = blockIdx.x & 3;
    int q64 = q * 64;
    int dim = (p < 12) ? 0 : 1;
    int img = (p < 12) ? p : p - 12;

    float ab = g_bd[img][dim][0][t],      ad = g_bd[img][dim][1][t];
    float bb = g_bd[12 + img][dim][0][t], bd = g_bd[12 + img][dim][1][t];
    float2 a = make_float2(ab, ad), b = make_float2(bb, bd);
    Ash[t] = a; Bsh[t] = b;
    float da = 0.5f * (ad - ab), db = 0.5f * (bd - bb);
    if (t < 4) sc[t] = (t < 2) ? 0.f : 1.f;
    EG[t] = 1.f;
    __syncthreads();

    float mC = fmaxf(da, db);
    #pragma unroll 4
    for (int i = 0; i < KTOP; ++i) {
        float2 aq = Ash[i];
        mC = fmaxf(mC, fmaxf(fabsf(aq.x - b.x), fabsf(aq.y - b.y)));
    }
    float eps = 0.02f * fmaxf(blkMax(mC, r8), 1e-6f);
    float ie = 1.f / eps;
    das[t] = da * ie; dbs[t] = db * ie;
    EDA[t] = __expf(-da * ie); EDB[t] = __expf(-db * ie);

    float4 rEf[16], rEg[16];
    #pragma unroll
    for (int k = 0; k < 16; ++k) {
        float2 b0 = Bsh[q64 + k * 4 + 0], b1 = Bsh[q64 + k * 4 + 1],
               b2 = Bsh[q64 + k * 4 + 2], b3 = Bsh[q64 + k * 4 + 3];
        rEf[k].x = __expf(-fmaxf(fabsf(a.x - b0.x), fabsf(a.y - b0.y)) * ie);
        rEf[k].y = __expf(-fmaxf(fabsf(a.x - b1.x), fabsf(a.y - b1.y)) * ie);
        rEf[k].z = __expf(-fmaxf(fabsf(a.x - b2.x), fabsf(a.y - b2.y)) * ie);
        rEf[k].w = __expf(-fmaxf(fabsf(a.x - b3.x), fabsf(a.y - b3.y)) * ie);
        float2 a0 = Ash[q64 + k * 4 + 0], a1 = Ash[q64 + k * 4 + 1],
               a2 = Ash[q64 + k * 4 + 2], a3 = Ash[q64 + k * 4 + 3];
        rEg[k].x = __expf(-fmaxf(fabsf(a0.x - b.x), fabsf(a0.y - b.y)) * ie);
        rEg[k].y = __expf(-fmaxf(fabsf(a1.x - b.x), fabsf(a1.y - b.y)) * ie);
        rEg[k].z = __expf(-fmaxf(fabsf(a2.x - b.x), fabsf(a2.y - b.y)) * ie);
        rEg[k].w = __expf(-fmaxf(fabsf(a3.x - b.x), fabsf(a3.y - b.y)) * ie);
    }
    __syncthreads();
    CLUSTER_SYNC();

    uint32_t pbf_addr = smem_u32(&pbf[q * 256 + t]);
    uint32_t pbg_addr = smem_u32(&pbg[q * 256 + t]);
    float K_G = 0.f, K_F = 0.f;
    float myEDA = EDA[t], myEDB = EDB[t];
    float gOld = 0.f;
    float phiF = 0.f, phiG = 0.f;
    const float4* EGv = (const float4*)(EG + q64);
    const float4* EFv = (const float4*)(EF + q64);

    for (int it = 0; it < SINK_ITERS; ++it) {
        bool doK = (it < 16) || ((it & 3) == 0);
        // ---- f half-iter ----
        float4 acc = make_float4(0.f, 0.f, 0.f, 0.f);
        #pragma unroll
        for (int k = 0; k < 16; ++k) {
            float4 g4 = EGv[k];
            acc.x = fmaf(g4.x, rEf[k].x, acc.x);
            acc.y = fmaf(g4.y, rEf[k].y, acc.y);
            acc.z = fmaf(g4.z, rEf[k].z, acc.z);
            acc.w = fmaf(g4.w, rEf[k].w, acc.w);
        }
        float s = (acc.x + acc.y) + (acc.z + acc.w);
        #pragma unroll
        for (int rr = 0; rr < CLU; ++rr) st_cluster_f32(pbf_addr, rr, s);
        if (t < 32) {
            float s2 = 0.f;
            #pragma unroll
            for (int k = 0; k < 8; ++k) { int j = t + k * 32; s2 = fmaf(EG[j], EDB[j], s2); }
            #pragma unroll
            for (int o = 16; o; o >>= 1) s2 += __shfl_xor_sync(0xffffffffu, s2, o);
            if (t == 0) sc[0] = -(K_G + __logf(s2 + 256.f * sc[3]));
        }
        CLUSTER_SYNC();
        {
            float S = ((pbf[t] + pbf[256 + t]) + (pbf[512 + t] + pbf[768 + t]))
                    + 256.f * sc[3] * myEDA;
            phiF = -(K_G + __logf(S));
        }
        if (doK) {
            float m2 = phiF;
            #pragma unroll
            for (int o = 16; o; o >>= 1) m2 = fmaxf(m2, __shfl_xor_sync(0xffffffffu, m2, o));
            if ((t & 31) == 0) r8[w] = m2;
            __syncthreads();
            K_F = r8[0];
            #pragma unroll
            for (int k = 1; k < 8; ++k) K_F = fmaxf(K_F, r8[k]);
        }
        EF[t] = __expf(phiF - K_F);
        if (t == 0) sc[2] = __expf(sc[0] - K_F);
        __syncthreads();

        // ---- g half-iter ----
        acc = make_float4(0.f, 0.f, 0.f, 0.f);
        #pragma unroll
        for (int k = 0; k < 16; ++k) {
            float4 f4 = EFv[k];
            acc.x = fmaf(f4.x, rEg[k].x, acc.x);
            acc.y = fmaf(f4.y, rEg[k].y, acc.y);
            acc.z = fmaf(f4.z, rEg[k].z, acc.z);
            acc.w = fmaf(f4.w, rEg[k].w, acc.w);
        }
        s = (acc.x + acc.y) + (acc.z + acc.w);
        #pragma unroll
        for (int rr = 0; rr < CLU; ++rr) st_cluster_f32(pbg_addr, rr, s);
        if (t < 32) {
            float s2 = 0.f;
            #pragma unroll
            for (int k = 0; k < 8; ++k) { int i = t + k * 32; s2 = fmaf(EF[i], EDA[i], s2); }
            #pragma unroll
            for (int o = 16; o; o >>= 1) s2 += __shfl_xor_sync(0xffffffffu, s2, o);
            if (t == 0) sc[1] = -(K_F + __logf(s2 + 256.f * sc[2]));
        }
        CLUSTER_SYNC();
        {
            float S = ((pbg[t] + pbg[256 + t]) + (pbg[512 + t] + pbg[768 + t]))
                    + 256.f * sc[2] * myEDB;
            phiG = -(K_F + __logf(S));
        }
        float maxd = 1e30f;
        if (doK) {
            float dlt = fabsf(phiG - gOld);
            gOld = phiG;
            float m2 = phiG;
            #pragma unroll
            for (int o = 16; o; o >>= 1) {
                m2 = fmaxf(m2, __shfl_xor_sync(0xffffffffu, m2, o));
                dlt = fmaxf(dlt, __shfl_xor_sync(0xffffffffu, dlt, o));
            }
            if ((t & 31) == 0) { r8[w] = m2; r8d[w] = dlt; }
            __syncthreads();
            K_G = r8[0]; maxd = r8d[0];
            #pragma unroll
            for (int k = 1; k < 8; ++k) {
                K_G = fmaxf(K_G, r8[k]);
                maxd = fmaxf(maxd, r8d[k]);
            }
        }
        EG[t] = __expf(phiG - K_G);
        if (t == 0) sc[3] = __expf(sc[1] - K_G);
        __syncthreads();
        if (doK && it >= MIN_ITERS && maxd < EXIT_TOL) break;   // uniform across ranks
    }

    F[t] = phiF; G[t] = phiG;
    __syncthreads();

    // ---- final cost partial ----
    float acc2 = 0.f;
    float myG = phiG;
    #pragma unroll 4
    for (int ii = 0; ii < 64; ++ii) {
        float2 aq = Ash[q64 + ii];
        float cs = fmaxf(fabsf(aq.x - b.x), fabsf(aq.y - b.y)) * ie;
        acc2 += __expf(F[q64 + ii] + myG - cs) * cs;
    }
    if (t < 64) {
        int i = q64 + t;
        acc2 += 256.f * __expf(F[i] + sc[1] - das[i]) * das[i];
        acc2 += 256.f * __expf(sc[0] + G[i] - dbs[i]) * dbs[i];
    }
    float tot = blkSum(acc2, r8);

    if (t == 0) {
        g_wpart[p * CLU + q] = tot * eps;
        __threadfence();
        int ticket = atomicAdd(&g_ctr, 1);
        if (ticket == NIMG * CLU - 1) {
            g_ctr = 0;
            float ssum = 0.f;
            for (int pp = 0; pp < NIMG; ++pp) {
                float w2 = 0.f;
                for (int qq = 0; qq < CLU; ++qq) w2 += g_wpart[pp * CLU + qq];
                ssum += w2;
            }
            out[0] = ssum * 0.25f;
        }
    }
}

extern "C" void kernel_launch(void* const* d_in, const int* in_sizes, int n_in,
                              void* d_out, int out_size) {
    (void)in_sizes; (void)n_in; (void)out_size;
    const float* x = (const float*)d_in[0];
    const int* y = (const int*)d_in[1];
    static bool attr_set = false;
    if (!attr_set) {
        cudaFuncSetAttribute(sinkhorn_kernel,
                             cudaFuncAttributeMaxDynamicSharedMemorySize,
                             SINK_SMEM_FLOATS * 4);
        attr_set = true;
    }
    pool_kernel<<<(NIMG * NPX + 255) / 256, 256>>>(x, y);
    diagram_kernel<<<48, 256>>>();
    sinkhorn_kernel<<<NIMG * CLU, 256, SINK_SMEM_FLOATS * 4>>>((float*)d_out);
}